// round 8
// baseline (speedup 1.0000x reference)
#include <cuda_runtime.h>
#include <cuda_bf16.h>
#include <cstdint>

#define BB 16
#define CC 64
#define HH 128
#define WW 128
#define HWD (HH*WW)            // 16384
#define CHW (CC*HWD)           // 1048576
#define NELEM (BB*CHW)         // 16777216
#define NGRP (BB*CC)           // 1024
#define WSZ (BB*CC*CC*9)       // 589824

// Scratch (device globals: allocation-free rule)
__device__ float g_buf1[NELEM];
__device__ float g_buf2[NELEM];
__device__ __align__(16) __nv_bfloat16 g_w1h[WSZ];
__device__ __align__(16) __nv_bfloat16 g_w1l[WSZ];
__device__ __align__(16) __nv_bfloat16 g_w2h[WSZ];
__device__ __align__(16) __nv_bfloat16 g_w2l[WSZ];
__device__ float g_mean[NGRP];
__device__ float g_rstd[NGRP];
__device__ float g_psum[NGRP * 64];    // [group][rowpair]
__device__ float g_psum2[NGRP * 64];

// ======================= PTX helpers (plain compute_103-safe) ==========
__device__ __forceinline__ uint32_t smem_u32(const void* p) {
    uint32_t a;
    asm("{ .reg .u64 t; cvta.to.shared.u64 t, %1; cvt.u32.u64 %0, t; }" : "=r"(a) : "l"(p));
    return a;
}
#define STS128(r0, r1, r2, r3, addr) \
    asm volatile("st.shared.v4.b32 [%0], {%1, %2, %3, %4};" \
        :: "r"(addr), "r"(r0), "r"(r1), "r"(r2), "r"(r3) : "memory")
#define LDSM4(r, addr) \
    asm volatile("ldmatrix.sync.aligned.m8n8.x4.shared.b16 {%0,%1,%2,%3}, [%4];" \
        : "=r"((r)[0]), "=r"((r)[1]), "=r"((r)[2]), "=r"((r)[3]) : "r"(addr))
#define MMA_BF16(d, a, b0, b1) \
    asm volatile("mma.sync.aligned.m16n8k16.row.col.f32.bf16.bf16.f32 " \
        "{%0,%1,%2,%3}, {%4,%5,%6,%7}, {%8,%9}, {%0,%1,%2,%3};" \
        : "+f"((d)[0]), "+f"((d)[1]), "+f"((d)[2]), "+f"((d)[3]) \
        : "r"((a)[0]), "r"((a)[1]), "r"((a)[2]), "r"((a)[3]), "r"(b0), "r"(b1))
#define CP_ASYNC16(dst, src) \
    asm volatile("cp.async.cg.shared.global [%0], [%1], 16;" :: "r"(dst), "l"(src) : "memory")
#define CP_COMMIT() asm volatile("cp.async.commit_group;" ::: "memory")
#define CP_WAIT(n)  asm volatile("cp.async.wait_group %0;" :: "n"(n) : "memory")
#define SWZ128(off) ((uint32_t)(off) ^ ((((uint32_t)(off)) >> 3) & 0x70u))

// ---- dynamic smem layout (bytes) ----
// A: [part(2)][krow(4)] planes of 130 px x 64 ci bf16 (SW128), padded to 17408
// B: ring of 3 buffers, each [kw(3)] tiles (one part) of 64co x 64ci (8192 B)
#define PLANE 17408
#define SMB_OFF (8 * PLANE)            // 139264
#define SMB_BUF 24576
#define SM_STAT (SMB_OFF + 3 * SMB_BUF)   // 212992
#define SM_PART (SM_STAT + 512)           // 213504
#define SMEM_TOTAL (SM_PART + 1024)       // 214528 (< 227 KB)

// ======================= weight prep: fp32 -> split bf16 ================
// dst layout: [b][tap(kh*3+kw)][co][ci]
__global__ void prep_w_kernel(const float* __restrict__ k1, const float* __restrict__ k2) {
    int gi = blockIdx.x * 256 + threadIdx.x;
    if (gi >= 2 * WSZ) return;
    const float* src; __nv_bfloat16 *dh, *dl; int i;
    if (gi < WSZ) { src = k1; dh = g_w1h; dl = g_w1l; i = gi; }
    else          { src = k2; dh = g_w2h; dl = g_w2l; i = gi - WSZ; }
    int ci = i & 63;
    int co = (i >> 6) & 63;
    int k9 = (i >> 12) % 9;
    int b  = (i >> 12) / 9;
    float w = src[(((b * 64 + co) * 64 + ci) * 9) + k9];
    __nv_bfloat16 h = __float2bfloat16(w);
    __nv_bfloat16 l = __float2bfloat16(w - __bfloat162float(h));
    dh[i] = h; dl[i] = l;
}

// ======================= conv via mma.sync bf16 split ===================
// CTA = (row-pair, batch). 8 warps = 2 rows x 4 M-tiles; warp 32px x 64co.
// 6 phases: (kh, part). part0 computes hh+lh with Bh; part1 computes hl with Bl.
// B staged through a 3-buffer cp.async ring, one phase ahead.
template<int PASS>
__global__ __launch_bounds__(256, 1)
void conv_mma_kernel(const float* __restrict__ x_ext) {
    extern __shared__ __align__(1024) char smem[];
    const uint32_t sb = smem_u32(smem);
    const int tid = threadIdx.x, lid = tid & 31, wid = tid >> 5;
    const int rp = blockIdx.x, y0 = rp * 2, b = blockIdx.y;
    const float* src = (PASS == 0) ? x_ext : g_buf1;
    const __nv_bfloat16* wh = (PASS == 0) ? g_w1h : g_w2h;
    const __nv_bfloat16* wl = (PASS == 0) ? g_w1l : g_w2l;
    float* dst = (PASS == 0) ? g_buf1 : g_buf2;

    float* smean = (float*)(smem + SM_STAT);
    float* srstd = smean + 64;

    if (PASS == 1) {
        if (tid < 64) {
            smean[tid] = g_mean[b * 64 + tid];
            srstd[tid] = g_rstd[b * 64 + tid];
        }
        __syncthreads();
    }

    // ---- B stage issue: one part (Bh or Bl), all 3 kw, into ring buffer ----
    auto issueB = [&](int kh, int part, int buf) {
#pragma unroll
        for (int kw = 0; kw < 3; ++kw) {
            const __nv_bfloat16* s = (part ? wl : wh)
                + (size_t)(b * 9 + kh * 3 + kw) * 4096;
            const uint32_t dstb = sb + SMB_OFF + buf * SMB_BUF + kw * 8192;
#pragma unroll
            for (int i = 0; i < 2; ++i) {
                const int chunk = i * 256 + tid;
                CP_ASYNC16(dstb + SWZ128(chunk * 16), s + chunk * 8);
            }
        }
        CP_COMMIT();
    };

    // ---- A stage: one kh-row (both parts), 130 px x 64 ci ----
    const int px = tid & 127;
    const int cihalf = (tid >> 7) * 32;
    auto stageA = [&](int krow) {
        const int grow = y0 + krow - 1;
        const bool vr = (unsigned)grow < 128u;
        const float* base = src + (size_t)b * CHW + (size_t)(vr ? grow : 0) * WW + px;
        const uint32_t ph = sb + (0 * 4 + krow) * PLANE;
        const uint32_t pl = sb + (1 * 4 + krow) * PLANE;
        const int ar = px + 1;
#pragma unroll
        for (int c8 = 0; c8 < 4; ++c8) {
            const int ci0 = cihalf + c8 * 8;
            float v[8];
#pragma unroll
            for (int j = 0; j < 8; ++j) {
                float t = vr ? __ldg(base + (size_t)(ci0 + j) * HWD) : 0.f;
                if (PASS == 1 && vr) {
                    t = (t - smean[ci0 + j]) * srstd[ci0 + j];
                    t = t >= 0.f ? t : 0.2f * t;
                }
                v[j] = t;
            }
            uint32_t hp[4], lp[4];
#pragma unroll
            for (int j = 0; j < 4; ++j) {
                __nv_bfloat16 h0 = __float2bfloat16(v[2*j]);
                __nv_bfloat16 h1 = __float2bfloat16(v[2*j+1]);
                __nv_bfloat16 l0 = __float2bfloat16(v[2*j]   - __bfloat162float(h0));
                __nv_bfloat16 l1 = __float2bfloat16(v[2*j+1] - __bfloat162float(h1));
                hp[j] = (uint32_t)__bfloat16_as_ushort(h0) | ((uint32_t)__bfloat16_as_ushort(h1) << 16);
                lp[j] = (uint32_t)__bfloat16_as_ushort(l0) | ((uint32_t)__bfloat16_as_ushort(l1) << 16);
            }
            const uint32_t off = SWZ128(ar * 128 + ci0 * 2);
            STS128(hp[0], hp[1], hp[2], hp[3], ph + off);
            STS128(lp[0], lp[1], lp[2], lp[3], pl + off);
        }
    };

    // prologue: first B group in flight, then stage A rows 0..1 + halos
    issueB(0, 0, 0);
    stageA(0);
    stageA(1);
    if (tid < 128) {   // zero halo rows ar=0 / ar=129, all 8 planes
        const int plane = tid >> 4;
        const int row = (tid & 8) ? 129 : 0;
        const int chunk = tid & 7;
        STS128(0u, 0u, 0u, 0u, sb + plane * PLANE + SWZ128(row * 128 + chunk * 16));
    }

    // ---------- warp tiling ----------
    const int rowsel = wid >> 2;
    const int m0 = (wid & 3) * 32;
    const int la_row = lid & 15;
    const int la_k   = (lid & 16) ? 8 : 0;
    const int lb_n   = (lid & 7) + ((lid & 16) ? 8 : 0);
    const int lb_k   = (lid & 8);

    float acc[2][8][4];
#pragma unroll
    for (int mt = 0; mt < 2; ++mt)
#pragma unroll
        for (int nt = 0; nt < 8; ++nt)
#pragma unroll
            for (int j = 0; j < 4; ++j) acc[mt][nt][j] = 0.f;

#pragma unroll 1
    for (int p = 0; p < 6; ++p) {
        const int kh = p >> 1, part = p & 1;
        if (p < 5) issueB((p + 1) >> 1, (p + 1) & 1, (p + 1) % 3);
        if (p == 0) stageA(2);
        if (p == 1) stageA(3);
        if (p < 5) { CP_WAIT(1); } else { CP_WAIT(0); }
        __syncthreads();   // B[p%3] ready for all; also publishes staged A rows

        const uint32_t bufbase = sb + SMB_OFF + (p % 3) * SMB_BUF;
        const uint32_t aplaneH = sb + (rowsel + kh) * PLANE;
        const uint32_t aplaneL = aplaneH + 4 * PLANE;

#pragma unroll 1
        for (int kw = 0; kw < 3; ++kw) {
            const uint32_t btile = bufbase + kw * 8192;
            const uint32_t arow = (uint32_t)(m0 + la_row + kw) * 128;
#pragma unroll
            for (int kt = 0; kt < 4; ++kt) {
                const uint32_t kcol = (uint32_t)(kt * 16 + la_k) * 2;
                const uint32_t bcol = (uint32_t)(kt * 16 + lb_k) * 2;
                uint32_t bf[4][4];
#pragma unroll
                for (int nt2 = 0; nt2 < 4; ++nt2) {
                    const uint32_t off = SWZ128((uint32_t)(nt2 * 16 + lb_n) * 128 + bcol);
                    LDSM4(bf[nt2], btile + off);
                }
                uint32_t afh[2][4];
#pragma unroll
                for (int mt = 0; mt < 2; ++mt) {
                    const uint32_t off = SWZ128(arow + (uint32_t)(mt * 16) * 128 + kcol);
                    LDSM4(afh[mt], aplaneH + off);
                }
                if (part == 0) {
                    uint32_t afl[2][4];
#pragma unroll
                    for (int mt = 0; mt < 2; ++mt) {
                        const uint32_t off = SWZ128(arow + (uint32_t)(mt * 16) * 128 + kcol);
                        LDSM4(afl[mt], aplaneL + off);
                    }
#pragma unroll
                    for (int mt = 0; mt < 2; ++mt) {
#pragma unroll
                        for (int nt2 = 0; nt2 < 4; ++nt2) {
                            MMA_BF16(acc[mt][nt2 * 2],     afh[mt], bf[nt2][0], bf[nt2][1]);
                            MMA_BF16(acc[mt][nt2 * 2 + 1], afh[mt], bf[nt2][2], bf[nt2][3]);
                            MMA_BF16(acc[mt][nt2 * 2],     afl[mt], bf[nt2][0], bf[nt2][1]);
                            MMA_BF16(acc[mt][nt2 * 2 + 1], afl[mt], bf[nt2][2], bf[nt2][3]);
                        }
                    }
                } else {
#pragma unroll
                    for (int mt = 0; mt < 2; ++mt) {
#pragma unroll
                        for (int nt2 = 0; nt2 < 4; ++nt2) {
                            MMA_BF16(acc[mt][nt2 * 2],     afh[mt], bf[nt2][0], bf[nt2][1]);
                            MMA_BF16(acc[mt][nt2 * 2 + 1], afh[mt], bf[nt2][2], bf[nt2][3]);
                        }
                    }
                }
            }
        }
        // no trailing sync: ring distance 3 guarantees buffer reuse safety
    }
    __syncthreads();   // all reads of A planes done before D aliases them

    // ---------- epilogue: acc -> smem D[2][64][132] -> gmem + IN partials ----
    float* D = (float*)smem;    // aliases A region
    {
        const int pr = lid >> 2, qc = 2 * (lid & 3);
#pragma unroll
        for (int mt = 0; mt < 2; ++mt) {
#pragma unroll
            for (int nt = 0; nt < 8; ++nt) {
                const int opx = m0 + mt * 16 + pr;
                const int co = nt * 8 + qc;
                float* dr = D + (size_t)(rowsel * 64 + co) * 132;
                dr[opx]            = acc[mt][nt][0];
                dr[132 + opx]      = acc[mt][nt][1];
                dr[opx + 8]        = acc[mt][nt][2];
                dr[132 + opx + 8]  = acc[mt][nt][3];
            }
        }
    }
    __syncthreads();
    {   // coalesced store
        const int co = tid >> 2;
        const int pxb = (tid & 3) * 32;
#pragma unroll
        for (int r = 0; r < 2; ++r) {
            float* op = dst + (size_t)b * CHW + (size_t)co * HWD + (y0 + r) * WW + pxb;
            const float* dr = D + (size_t)(r * 64 + co) * 132 + pxb;
#pragma unroll
            for (int i = 0; i < 8; ++i)
                *(float4*)(op + i * 4) = *(const float4*)(dr + i * 4);
        }
    }
    {   // instance-norm partials: thread t -> (r, co, half)
        const int r = tid >> 7, co = (tid >> 1) & 63, half = tid & 1;
        const float* dr = D + (size_t)(r * 64 + co) * 132 + half * 64;
        float s = 0.f, s2 = 0.f;
#pragma unroll
        for (int i = 0; i < 64; ++i) { float v = dr[i]; s += v; s2 += v * v; }
        s  += __shfl_xor_sync(0xffffffffu, s, 1);
        s2 += __shfl_xor_sync(0xffffffffu, s2, 1);
        if (half == 0) {
            float* P = (float*)(smem + SM_PART);
            P[r * 64 + co]       = s;
            P[128 + r * 64 + co] = s2;
        }
    }
    __syncthreads();
    if (tid < 64) {
        const float* P = (float*)(smem + SM_PART);
        const int g = b * 64 + tid;
        g_psum [g * 64 + rp] = P[tid] + P[64 + tid];
        g_psum2[g * 64 + rp] = P[128 + tid] + P[192 + tid];
    }
}

// ======================= stats reduce: 64 partials per group ============
__global__ void stats_reduce_kernel() {
    const int g = blockIdx.x;
    const int l = threadIdx.x;          // 32 threads
    float s  = g_psum [g * 64 + 2 * l] + g_psum [g * 64 + 2 * l + 1];
    float s2 = g_psum2[g * 64 + 2 * l] + g_psum2[g * 64 + 2 * l + 1];
#pragma unroll
    for (int o = 16; o; o >>= 1) {
        s  += __shfl_xor_sync(0xffffffffu, s, o);
        s2 += __shfl_xor_sync(0xffffffffu, s2, o);
    }
    if (l == 0) {
        const float inv = 1.f / (float)HWD;
        float m = s * inv;
        float var = s2 * inv - m * m;
        g_mean[g] = m;
        g_rstd[g] = rsqrtf(var + 1e-5f);
    }
}

__device__ __forceinline__ float lrelu(float v) { return v >= 0.f ? v : 0.2f * v; }

// ---------- out = lrelu(x + IN(buf2)) ----------
__global__ void final_kernel(const float* __restrict__ x, float* __restrict__ out) {
    const int i = blockIdx.x * 256 + threadIdx.x;      // float4 index
    float4 v  = ((const float4*)g_buf2)[i];
    float4 xv = ((const float4*)x)[i];
    const int g = i >> 12;
    const float m = g_mean[g], rs = g_rstd[g];
    float4 o;
    o.x = lrelu(xv.x + (v.x - m) * rs);
    o.y = lrelu(xv.y + (v.y - m) * rs);
    o.z = lrelu(xv.z + (v.z - m) * rs);
    o.w = lrelu(xv.w + (v.w - m) * rs);
    ((float4*)out)[i] = o;
}

extern "C" void kernel_launch(void* const* d_in, const int* in_sizes, int n_in,
                              void* d_out, int out_size) {
    const float* x  = (const float*)d_in[0];
    const float* k1 = (const float*)d_in[1];
    const float* k2 = (const float*)d_in[2];
    float* out = (float*)d_out;

    cudaFuncSetAttribute(conv_mma_kernel<0>, cudaFuncAttributeMaxDynamicSharedMemorySize, SMEM_TOTAL);
    cudaFuncSetAttribute(conv_mma_kernel<1>, cudaFuncAttributeMaxDynamicSharedMemorySize, SMEM_TOTAL);

    prep_w_kernel<<<(2 * WSZ + 255) / 256, 256>>>(k1, k2);

    dim3 grid(HH / 2, BB);   // (row-pair, batch)
    conv_mma_kernel<0><<<grid, 256, SMEM_TOTAL>>>(x);
    stats_reduce_kernel<<<NGRP, 32>>>();
    conv_mma_kernel<1><<<grid, 256, SMEM_TOTAL>>>(x);
    stats_reduce_kernel<<<NGRP, 32>>>();
    final_kernel<<<NELEM / 1024, 256>>>(x, out);
}

// round 9
// speedup vs baseline: 1.0600x; 1.0600x over previous
#include <cuda_runtime.h>
#include <cuda_bf16.h>
#include <cstdint>

#define BB 16
#define CC 64
#define HH 128
#define WW 128
#define HWD (HH*WW)            // 16384
#define CHW (CC*HWD)           // 1048576
#define NELEM (BB*CHW)         // 16777216
#define NGRP (BB*CC)           // 1024
#define WSZ (BB*CC*CC*9)       // 589824

// Scratch (device globals: allocation-free rule)
__device__ float g_buf1[NELEM];
__device__ float g_buf2[NELEM];
__device__ __align__(16) __nv_bfloat16 g_w1h[WSZ];
__device__ __align__(16) __nv_bfloat16 g_w1l[WSZ];
__device__ __align__(16) __nv_bfloat16 g_w2h[WSZ];
__device__ __align__(16) __nv_bfloat16 g_w2l[WSZ];
__device__ float g_mean[NGRP];
__device__ float g_rstd[NGRP];
__device__ float g_psum[NGRP * 64];    // [group][rowpair]
__device__ float g_psum2[NGRP * 64];

// ======================= PTX helpers (plain compute_103-safe) ==========
__device__ __forceinline__ uint32_t smem_u32(const void* p) {
    uint32_t a;
    asm("{ .reg .u64 t; cvta.to.shared.u64 t, %1; cvt.u32.u64 %0, t; }" : "=r"(a) : "l"(p));
    return a;
}
#define STS128(r0, r1, r2, r3, addr) \
    asm volatile("st.shared.v4.b32 [%0], {%1, %2, %3, %4};" \
        :: "r"(addr), "r"(r0), "r"(r1), "r"(r2), "r"(r3) : "memory")
#define LDSM4(r, addr) \
    asm volatile("ldmatrix.sync.aligned.m8n8.x4.shared.b16 {%0,%1,%2,%3}, [%4];" \
        : "=r"((r)[0]), "=r"((r)[1]), "=r"((r)[2]), "=r"((r)[3]) : "r"(addr))
#define MMA_BF16(d, a, b0, b1) \
    asm volatile("mma.sync.aligned.m16n8k16.row.col.f32.bf16.bf16.f32 " \
        "{%0,%1,%2,%3}, {%4,%5,%6,%7}, {%8,%9}, {%0,%1,%2,%3};" \
        : "+f"((d)[0]), "+f"((d)[1]), "+f"((d)[2]), "+f"((d)[3]) \
        : "r"((a)[0]), "r"((a)[1]), "r"((a)[2]), "r"((a)[3]), "r"(b0), "r"(b1))
#define CP_ASYNC16(dst, src) \
    asm volatile("cp.async.cg.shared.global [%0], [%1], 16;" :: "r"(dst), "l"(src) : "memory")
#define CP_COMMIT() asm volatile("cp.async.commit_group;" ::: "memory")
#define CP_WAIT(n)  asm volatile("cp.async.wait_group %0;" :: "n"(n) : "memory")
#define SWZ128(off) ((uint32_t)(off) ^ ((((uint32_t)(off)) >> 3) & 0x70u))

// ---- dynamic smem layout (bytes) ----
// A: [part(2)][krow(4)] planes of 130 px x 64 ci bf16, stride 16640 (mult of 128:
//    SW128 conflict pattern is translation-invariant under +256 base shifts)
// B: 2 buffers of [kw(3)][part(2)] tiles 64co x 64ci bf16 (8192 B each) = 48 KB
// stats alias start of B buf1 (prologue-only); partials alias B buf0 (epilogue-only)
#define PLANE 16640
#define SMB_OFF (8 * PLANE)              // 133120
#define SMB_BUF 49152
#define SM_STAT (SMB_OFF + SMB_BUF)      // buf1 start (prologue-only use)
#define SM_PART (SMB_OFF)                // buf0 start (epilogue-only use)
#define SMEM_TOTAL (SMB_OFF + 2 * SMB_BUF)   // 231424 = 226 KB (< 227 KB cap)

// ======================= weight prep: fp32 -> split bf16 ================
// dst layout: [b][tap(kh*3+kw)][co][ci]
__global__ void prep_w_kernel(const float* __restrict__ k1, const float* __restrict__ k2) {
    int gi = blockIdx.x * 256 + threadIdx.x;
    if (gi >= 2 * WSZ) return;
    const float* src; __nv_bfloat16 *dh, *dl; int i;
    if (gi < WSZ) { src = k1; dh = g_w1h; dl = g_w1l; i = gi; }
    else          { src = k2; dh = g_w2h; dl = g_w2l; i = gi - WSZ; }
    int ci = i & 63;
    int co = (i >> 6) & 63;
    int k9 = (i >> 12) % 9;
    int b  = (i >> 12) / 9;
    float w = src[(((b * 64 + co) * 64 + ci) * 9) + k9];
    __nv_bfloat16 h = __float2bfloat16(w);
    __nv_bfloat16 l = __float2bfloat16(w - __bfloat162float(h));
    dh[i] = h; dl[i] = l;
}

// ======================= conv via mma.sync bf16 split ===================
// CTA = (row-pair, batch). 8 warps = 2 rows x 4 M-tiles; warp 32px x 64co.
// 3 phases (kh). B double-buffered: B(kh+1) cp.async issued at top of phase kh,
// waited at top of phase kh+1 -> load fully hidden behind ~576 MMAs of compute.
// MMA ordering is term-major (hh-all, lh-all, hl-all) per (kw,kt): same-acc
// reuse distance 32 MMAs >> HMMA latency.
template<int PASS>
__global__ __launch_bounds__(256, 1)
void conv_mma_kernel(const float* __restrict__ x_ext) {
    extern __shared__ __align__(1024) char smem[];
    const uint32_t sb = smem_u32(smem);
    const int tid = threadIdx.x, lid = tid & 31, wid = tid >> 5;
    const int rp = blockIdx.x, y0 = rp * 2, b = blockIdx.y;
    const float* src = (PASS == 0) ? x_ext : g_buf1;
    const __nv_bfloat16* wh = (PASS == 0) ? g_w1h : g_w2h;
    const __nv_bfloat16* wl = (PASS == 0) ? g_w1l : g_w2l;
    float* dst = (PASS == 0) ? g_buf1 : g_buf2;

    float* smean = (float*)(smem + SM_STAT);   // aliases B buf1 (prologue only)
    float* srstd = smean + 64;

    if (PASS == 1) {
        if (tid < 64) {
            smean[tid] = g_mean[b * 64 + tid];
            srstd[tid] = g_rstd[b * 64 + tid];
        }
        __syncthreads();
    }

    // ---- B stage issue: both parts, all 3 kw (48 KB) into buffer buf ----
    auto issueB = [&](int kh, int buf) {
#pragma unroll
        for (int kw = 0; kw < 3; ++kw) {
#pragma unroll
            for (int part = 0; part < 2; ++part) {
                const __nv_bfloat16* s = (part ? wl : wh)
                    + (size_t)(b * 9 + kh * 3 + kw) * 4096;
                const uint32_t dstb = sb + SMB_OFF + buf * SMB_BUF
                                    + kw * 16384 + part * 8192;
#pragma unroll
                for (int i = 0; i < 2; ++i) {
                    const int chunk = i * 256 + tid;
                    CP_ASYNC16(dstb + SWZ128(chunk * 16), s + chunk * 8);
                }
            }
        }
        CP_COMMIT();
    };

    // prologue: B(0) in flight while A stages
    issueB(0, 0);

    // ---------- stage A: 4 kh-rows x 130 px x 64 ci, hi+lo ----------
    {
        const int px = tid & 127;
        const int cihalf = (tid >> 7) * 32;
        const int ar = px + 1;
#pragma unroll
        for (int krow = 0; krow < 4; ++krow) {
            const int grow = y0 + krow - 1;
            const bool vr = (unsigned)grow < 128u;
            const float* base = src + (size_t)b * CHW + (size_t)(vr ? grow : 0) * WW + px;
            const uint32_t ph = sb + (0 * 4 + krow) * PLANE;
            const uint32_t pl = sb + (1 * 4 + krow) * PLANE;
#pragma unroll
            for (int c8 = 0; c8 < 4; ++c8) {
                const int ci0 = cihalf + c8 * 8;
                float v[8];
#pragma unroll
                for (int j = 0; j < 8; ++j) {
                    float t = vr ? __ldg(base + (size_t)(ci0 + j) * HWD) : 0.f;
                    if (PASS == 1 && vr) {
                        t = (t - smean[ci0 + j]) * srstd[ci0 + j];
                        t = t >= 0.f ? t : 0.2f * t;
                    }
                    v[j] = t;
                }
                uint32_t hp[4], lp[4];
#pragma unroll
                for (int j = 0; j < 4; ++j) {
                    __nv_bfloat16 h0 = __float2bfloat16(v[2*j]);
                    __nv_bfloat16 h1 = __float2bfloat16(v[2*j+1]);
                    __nv_bfloat16 l0 = __float2bfloat16(v[2*j]   - __bfloat162float(h0));
                    __nv_bfloat16 l1 = __float2bfloat16(v[2*j+1] - __bfloat162float(h1));
                    hp[j] = (uint32_t)__bfloat16_as_ushort(h0) | ((uint32_t)__bfloat16_as_ushort(h1) << 16);
                    lp[j] = (uint32_t)__bfloat16_as_ushort(l0) | ((uint32_t)__bfloat16_as_ushort(l1) << 16);
                }
                const uint32_t off = SWZ128(ar * 128 + ci0 * 2);
                STS128(hp[0], hp[1], hp[2], hp[3], ph + off);
                STS128(lp[0], lp[1], lp[2], lp[3], pl + off);
            }
        }
        if (tid < 128) {   // zero halo rows ar=0 / ar=129, all 8 planes
            const int plane = tid >> 4;
            const int row = (tid & 8) ? 129 : 0;
            const int chunk = tid & 7;
            STS128(0u, 0u, 0u, 0u, sb + plane * PLANE + SWZ128(row * 128 + chunk * 16));
        }
    }

    // ---------- warp tiling ----------
    const int rowsel = wid >> 2;
    const int m0 = (wid & 3) * 32;
    const int la_row = lid & 15;
    const int la_k   = (lid & 16) ? 8 : 0;
    const int lb_n   = (lid & 7) + ((lid & 16) ? 8 : 0);
    const int lb_k   = (lid & 8);

    float acc[2][8][4];
#pragma unroll
    for (int mt = 0; mt < 2; ++mt)
#pragma unroll
        for (int nt = 0; nt < 8; ++nt)
#pragma unroll
            for (int j = 0; j < 4; ++j) acc[mt][nt][j] = 0.f;

#pragma unroll 1
    for (int kh = 0; kh < 3; ++kh) {
        CP_WAIT(0);
        __syncthreads();   // B(kh) visible to all; phase kh-1 readers done with other buf
        if (kh < 2) issueB(kh + 1, (kh + 1) & 1);   // in flight during compute below

        const uint32_t bufbase = sb + SMB_OFF + (kh & 1) * SMB_BUF;
        const uint32_t aplaneH = sb + (rowsel + kh) * PLANE;
        const uint32_t aplaneL = aplaneH + 4 * PLANE;

#pragma unroll 1
        for (int kw = 0; kw < 3; ++kw) {
            const uint32_t btileH = bufbase + kw * 16384;
            const uint32_t btileL = btileH + 8192;
            const uint32_t arow = (uint32_t)(m0 + la_row + kw) * 128;
#pragma unroll
            for (int kt = 0; kt < 4; ++kt) {
                const uint32_t kcol = (uint32_t)(kt * 16 + la_k) * 2;
                const uint32_t bcol = (uint32_t)(kt * 16 + lb_k) * 2;
                uint32_t afh[2][4], afl[2][4];
#pragma unroll
                for (int mt = 0; mt < 2; ++mt) {
                    const uint32_t off = SWZ128(arow + (uint32_t)(mt * 16) * 128 + kcol);
                    LDSM4(afh[mt], aplaneH + off);
                    LDSM4(afl[mt], aplaneL + off);
                }
                uint32_t bfh[4][4], bfl[4][4];
#pragma unroll
                for (int nt2 = 0; nt2 < 4; ++nt2) {
                    const uint32_t off = SWZ128((uint32_t)(nt2 * 16 + lb_n) * 128 + bcol);
                    LDSM4(bfh[nt2], btileH + off);
                    LDSM4(bfl[nt2], btileL + off);
                }
                // term-major: same-acc reuse distance = 32 MMAs
#pragma unroll
                for (int mt = 0; mt < 2; ++mt)
#pragma unroll
                    for (int nt2 = 0; nt2 < 4; ++nt2) {
                        MMA_BF16(acc[mt][nt2 * 2],     afh[mt], bfh[nt2][0], bfh[nt2][1]);
                        MMA_BF16(acc[mt][nt2 * 2 + 1], afh[mt], bfh[nt2][2], bfh[nt2][3]);
                    }
#pragma unroll
                for (int mt = 0; mt < 2; ++mt)
#pragma unroll
                    for (int nt2 = 0; nt2 < 4; ++nt2) {
                        MMA_BF16(acc[mt][nt2 * 2],     afl[mt], bfh[nt2][0], bfh[nt2][1]);
                        MMA_BF16(acc[mt][nt2 * 2 + 1], afl[mt], bfh[nt2][2], bfh[nt2][3]);
                    }
#pragma unroll
                for (int mt = 0; mt < 2; ++mt)
#pragma unroll
                    for (int nt2 = 0; nt2 < 4; ++nt2) {
                        MMA_BF16(acc[mt][nt2 * 2],     afh[mt], bfl[nt2][0], bfl[nt2][1]);
                        MMA_BF16(acc[mt][nt2 * 2 + 1], afh[mt], bfl[nt2][2], bfl[nt2][3]);
                    }
            }
        }
        // no trailing sync: next phase's top sync covers buffer-reuse safety
    }
    __syncthreads();   // all LDSM reads of A planes done before D aliases them

    // ---------- epilogue: acc -> smem D[2][64][132] -> gmem + IN partials ----
    float* D = (float*)smem;    // aliases A region
    {
        const int pr = lid >> 2, qc = 2 * (lid & 3);
#pragma unroll
        for (int mt = 0; mt < 2; ++mt) {
#pragma unroll
            for (int nt = 0; nt < 8; ++nt) {
                const int opx = m0 + mt * 16 + pr;
                const int co = nt * 8 + qc;
                float* dr = D + (size_t)(rowsel * 64 + co) * 132;
                dr[opx]            = acc[mt][nt][0];
                dr[132 + opx]      = acc[mt][nt][1];
                dr[opx + 8]        = acc[mt][nt][2];
                dr[132 + opx + 8]  = acc[mt][nt][3];
            }
        }
    }
    __syncthreads();
    {   // coalesced store
        const int co = tid >> 2;
        const int pxb = (tid & 3) * 32;
#pragma unroll
        for (int r = 0; r < 2; ++r) {
            float* op = dst + (size_t)b * CHW + (size_t)co * HWD + (y0 + r) * WW + pxb;
            const float* dr = D + (size_t)(r * 64 + co) * 132 + pxb;
#pragma unroll
            for (int i = 0; i < 8; ++i)
                *(float4*)(op + i * 4) = *(const float4*)(dr + i * 4);
        }
    }
    {   // instance-norm partials: thread t -> (r, co, half)
        const int r = tid >> 7, co = (tid >> 1) & 63, half = tid & 1;
        const float* dr = D + (size_t)(r * 64 + co) * 132 + half * 64;
        float s = 0.f, s2 = 0.f;
#pragma unroll
        for (int i = 0; i < 64; ++i) { float v = dr[i]; s += v; s2 += v * v; }
        s  += __shfl_xor_sync(0xffffffffu, s, 1);
        s2 += __shfl_xor_sync(0xffffffffu, s2, 1);
        if (half == 0) {
            float* P = (float*)(smem + SM_PART);   // aliases B buf0 (done)
            P[r * 64 + co]       = s;
            P[128 + r * 64 + co] = s2;
        }
    }
    __syncthreads();
    if (tid < 64) {
        const float* P = (float*)(smem + SM_PART);
        const int g = b * 64 + tid;
        g_psum [g * 64 + rp] = P[tid] + P[64 + tid];
        g_psum2[g * 64 + rp] = P[128 + tid] + P[192 + tid];
    }
}

// ======================= stats reduce: 64 partials per group ============
__global__ void stats_reduce_kernel() {
    const int g = blockIdx.x;
    const int l = threadIdx.x;          // 32 threads
    float s  = g_psum [g * 64 + 2 * l] + g_psum [g * 64 + 2 * l + 1];
    float s2 = g_psum2[g * 64 + 2 * l] + g_psum2[g * 64 + 2 * l + 1];
#pragma unroll
    for (int o = 16; o; o >>= 1) {
        s  += __shfl_xor_sync(0xffffffffu, s, o);
        s2 += __shfl_xor_sync(0xffffffffu, s2, o);
    }
    if (l == 0) {
        const float inv = 1.f / (float)HWD;
        float m = s * inv;
        float var = s2 * inv - m * m;
        g_mean[g] = m;
        g_rstd[g] = rsqrtf(var + 1e-5f);
    }
}

__device__ __forceinline__ float lrelu(float v) { return v >= 0.f ? v : 0.2f * v; }

// ---------- out = lrelu(x + IN(buf2)) ----------
__global__ void final_kernel(const float* __restrict__ x, float* __restrict__ out) {
    const int i = blockIdx.x * 256 + threadIdx.x;      // float4 index
    float4 v  = ((const float4*)g_buf2)[i];
    float4 xv = ((const float4*)x)[i];
    const int g = i >> 12;
    const float m = g_mean[g], rs = g_rstd[g];
    float4 o;
    o.x = lrelu(xv.x + (v.x - m) * rs);
    o.y = lrelu(xv.y + (v.y - m) * rs);
    o.z = lrelu(xv.z + (v.z - m) * rs);
    o.w = lrelu(xv.w + (v.w - m) * rs);
    ((float4*)out)[i] = o;
}

extern "C" void kernel_launch(void* const* d_in, const int* in_sizes, int n_in,
                              void* d_out, int out_size) {
    const float* x  = (const float*)d_in[0];
    const float* k1 = (const float*)d_in[1];
    const float* k2 = (const float*)d_in[2];
    float* out = (float*)d_out;

    cudaFuncSetAttribute(conv_mma_kernel<0>, cudaFuncAttributeMaxDynamicSharedMemorySize, SMEM_TOTAL);
    cudaFuncSetAttribute(conv_mma_kernel<1>, cudaFuncAttributeMaxDynamicSharedMemorySize, SMEM_TOTAL);

    prep_w_kernel<<<(2 * WSZ + 255) / 256, 256>>>(k1, k2);

    dim3 grid(HH / 2, BB);   // (row-pair, batch)
    conv_mma_kernel<0><<<grid, 256, SMEM_TOTAL>>>(x);
    stats_reduce_kernel<<<NGRP, 32>>>();
    conv_mma_kernel<1><<<grid, 256, SMEM_TOTAL>>>(x);
    stats_reduce_kernel<<<NGRP, 32>>>();
    final_kernel<<<NELEM / 1024, 256>>>(x, out);
}

// round 10
// speedup vs baseline: 1.0707x; 1.0101x over previous
#include <cuda_runtime.h>
#include <cuda_bf16.h>
#include <cstdint>

#define BB 16
#define CC 64
#define HH 128
#define WW 128
#define HWD (HH*WW)            // 16384
#define CHW (CC*HWD)           // 1048576
#define NELEM (BB*CHW)         // 16777216
#define NGRP (BB*CC)           // 1024
#define WSZ (BB*CC*CC*9)       // 589824

// Scratch (device globals: allocation-free rule)
__device__ float g_buf1[NELEM];
__device__ float g_buf2[NELEM];
__device__ __align__(16) __nv_bfloat16 g_w1h[WSZ];
__device__ __align__(16) __nv_bfloat16 g_w1l[WSZ];
__device__ __align__(16) __nv_bfloat16 g_w2h[WSZ];
__device__ __align__(16) __nv_bfloat16 g_w2l[WSZ];
__device__ float g_mean[NGRP];
__device__ float g_rstd[NGRP];
__device__ float g_psum[NGRP * 64];    // [group][rowpair]
__device__ float g_psum2[NGRP * 64];

// ======================= PTX helpers (plain compute_103-safe) ==========
__device__ __forceinline__ uint32_t smem_u32(const void* p) {
    uint32_t a;
    asm("{ .reg .u64 t; cvta.to.shared.u64 t, %1; cvt.u32.u64 %0, t; }" : "=r"(a) : "l"(p));
    return a;
}
#define STS128(r0, r1, r2, r3, addr) \
    asm volatile("st.shared.v4.b32 [%0], {%1, %2, %3, %4};" \
        :: "r"(addr), "r"(r0), "r"(r1), "r"(r2), "r"(r3) : "memory")
#define LDSM4(r, addr) \
    asm volatile("ldmatrix.sync.aligned.m8n8.x4.shared.b16 {%0,%1,%2,%3}, [%4];" \
        : "=r"((r)[0]), "=r"((r)[1]), "=r"((r)[2]), "=r"((r)[3]) : "r"(addr))
#define MMA_BF16(d, a, b0, b1) \
    asm volatile("mma.sync.aligned.m16n8k16.row.col.f32.bf16.bf16.f32 " \
        "{%0,%1,%2,%3}, {%4,%5,%6,%7}, {%8,%9}, {%0,%1,%2,%3};" \
        : "+f"((d)[0]), "+f"((d)[1]), "+f"((d)[2]), "+f"((d)[3]) \
        : "r"((a)[0]), "r"((a)[1]), "r"((a)[2]), "r"((a)[3]), "r"(b0), "r"(b1))
#define CP_ASYNC16(dst, src) \
    asm volatile("cp.async.cg.shared.global [%0], [%1], 16;" :: "r"(dst), "l"(src) : "memory")
#define CP_COMMIT() asm volatile("cp.async.commit_group;" ::: "memory")
#define CP_WAIT(n)  asm volatile("cp.async.wait_group %0;" :: "n"(n) : "memory")
#define SWZ128(off) ((uint32_t)(off) ^ ((((uint32_t)(off)) >> 3) & 0x70u))

// ---- dynamic smem layout (bytes) ----
// A: [part(2)][krow(4)] planes of 130 px x 64 ci bf16, stride 16640
// B: 2 buffers of [kw(3)][part(2)] tiles 64co x 64ci bf16 (8192 B each) = 48 KB
// stats alias start of B buf1 (prologue-only); partials alias B buf0 (epilogue-only)
#define PLANE 16640
#define SMB_OFF (8 * PLANE)              // 133120
#define SMB_BUF 49152
#define SM_STAT (SMB_OFF + SMB_BUF)      // buf1 start (prologue-only use)
#define SM_PART (SMB_OFF)                // buf0 start (epilogue-only use)
#define SMEM_TOTAL (SMB_OFF + 2 * SMB_BUF)   // 231424 (< 227 KB cap = 232448)

#define NTHREADS 512

// ======================= weight prep: fp32 -> split bf16 ================
// dst layout: [b][tap(kh*3+kw)][co][ci]
__global__ void prep_w_kernel(const float* __restrict__ k1, const float* __restrict__ k2) {
    int gi = blockIdx.x * 256 + threadIdx.x;
    if (gi >= 2 * WSZ) return;
    const float* src; __nv_bfloat16 *dh, *dl; int i;
    if (gi < WSZ) { src = k1; dh = g_w1h; dl = g_w1l; i = gi; }
    else          { src = k2; dh = g_w2h; dl = g_w2l; i = gi - WSZ; }
    int ci = i & 63;
    int co = (i >> 6) & 63;
    int k9 = (i >> 12) % 9;
    int b  = (i >> 12) / 9;
    float w = src[(((b * 64 + co) * 64 + ci) * 9) + k9];
    __nv_bfloat16 h = __float2bfloat16(w);
    __nv_bfloat16 l = __float2bfloat16(w - __bfloat162float(h));
    dh[i] = h; dl[i] = l;
}

// ======================= conv via mma.sync bf16 split ===================
// CTA = (row-pair, batch), 512 threads = 16 warps (4/SMSP for latency hiding).
// Warp tile 16px x 64co. 3 phases (kh), B double-buffered via cp.async.
// Per (kw,kt): 10 LDSM feed 24 MMAs, term-major (hh, lh, hl).
template<int PASS>
__global__ __launch_bounds__(NTHREADS, 1)
void conv_mma_kernel(const float* __restrict__ x_ext) {
    extern __shared__ __align__(1024) char smem[];
    const uint32_t sb = smem_u32(smem);
    const int tid = threadIdx.x, lid = tid & 31, wid = tid >> 5;
    const int rp = blockIdx.x, y0 = rp * 2, b = blockIdx.y;
    const float* src = (PASS == 0) ? x_ext : g_buf1;
    const __nv_bfloat16* wh = (PASS == 0) ? g_w1h : g_w2h;
    const __nv_bfloat16* wl = (PASS == 0) ? g_w1l : g_w2l;
    float* dst = (PASS == 0) ? g_buf1 : g_buf2;

    float* smean = (float*)(smem + SM_STAT);   // aliases B buf1 (prologue only)
    float* srstd = smean + 64;

    if (PASS == 1) {
        if (tid < 64) {
            smean[tid] = g_mean[b * 64 + tid];
            srstd[tid] = g_rstd[b * 64 + tid];
        }
        __syncthreads();
    }

    // ---- B stage issue: both parts, all 3 kw (48 KB) into buffer buf ----
    auto issueB = [&](int kh, int buf) {
#pragma unroll
        for (int kw = 0; kw < 3; ++kw) {
#pragma unroll
            for (int part = 0; part < 2; ++part) {
                const __nv_bfloat16* s = (part ? wl : wh)
                    + (size_t)(b * 9 + kh * 3 + kw) * 4096;
                const uint32_t dstb = sb + SMB_OFF + buf * SMB_BUF
                                    + kw * 16384 + part * 8192;
                // 512 threads x 16B = 8192 B in one sweep
                CP_ASYNC16(dstb + SWZ128(tid * 16), s + tid * 8);
            }
        }
        CP_COMMIT();
    };

    // prologue: B(0) in flight while A stages
    issueB(0, 0);

    // ---------- stage A: 4 kh-rows x 130 px x 64 ci, hi+lo ----------
    // hi = truncated top-16 bits (PRMT, no cvt); lo = rn(f - hi) via bf16x2 cvt.
    {
        const int px = tid & 127;
        const int cihalf = (tid >> 7) * 16;    // 4 groups of 16 ci
        const int ar = px + 1;
#pragma unroll
        for (int krow = 0; krow < 4; ++krow) {
            const int grow = y0 + krow - 1;
            const bool vr = (unsigned)grow < 128u;
            const float* base = src + (size_t)b * CHW + (size_t)(vr ? grow : 0) * WW + px;
            const uint32_t ph = sb + (0 * 4 + krow) * PLANE;
            const uint32_t pl = sb + (1 * 4 + krow) * PLANE;
#pragma unroll
            for (int c8 = 0; c8 < 2; ++c8) {
                const int ci0 = cihalf + c8 * 8;
                float v[8];
#pragma unroll
                for (int j = 0; j < 8; ++j) {
                    float t = vr ? __ldg(base + (size_t)(ci0 + j) * HWD) : 0.f;
                    if (PASS == 1 && vr) {
                        t = (t - smean[ci0 + j]) * srstd[ci0 + j];
                        t = t >= 0.f ? t : 0.2f * t;
                    }
                    v[j] = t;
                }
                uint32_t hp[4], lp[4];
#pragma unroll
                for (int j = 0; j < 4; ++j) {
                    const uint32_t u0 = __float_as_uint(v[2*j]);
                    const uint32_t u1 = __float_as_uint(v[2*j+1]);
                    hp[j] = __byte_perm(u0, u1, 0x7632);   // {hi16(u0), hi16(u1)}
                    const float h0 = __uint_as_float(u0 & 0xFFFF0000u);
                    const float h1 = __uint_as_float(u1 & 0xFFFF0000u);
                    asm("cvt.rn.bf16x2.f32 %0, %1, %2;"
                        : "=r"(lp[j]) : "f"(v[2*j+1] - h1), "f"(v[2*j] - h0));
                }
                const uint32_t off = SWZ128(ar * 128 + ci0 * 2);
                STS128(hp[0], hp[1], hp[2], hp[3], ph + off);
                STS128(lp[0], lp[1], lp[2], lp[3], pl + off);
            }
        }
        if (tid < 128) {   // zero halo rows ar=0 / ar=129, all 8 planes
            const int plane = tid >> 4;
            const int row = (tid & 8) ? 129 : 0;
            const int chunk = tid & 7;
            STS128(0u, 0u, 0u, 0u, sb + plane * PLANE + SWZ128(row * 128 + chunk * 16));
        }
    }

    // ---------- warp tiling: 16 warps = 2 rows x 8 M-tiles of 16 px ----------
    const int rowsel = wid >> 3;
    const int m0 = (wid & 7) * 16;
    const int la_row = lid & 15;
    const int la_k   = (lid & 16) ? 8 : 0;
    const int lb_n   = (lid & 7) + ((lid & 16) ? 8 : 0);
    const int lb_k   = (lid & 8);

    float acc[8][4];
#pragma unroll
    for (int nt = 0; nt < 8; ++nt)
#pragma unroll
        for (int j = 0; j < 4; ++j) acc[nt][j] = 0.f;

#pragma unroll 1
    for (int kh = 0; kh < 3; ++kh) {
        CP_WAIT(0);
        __syncthreads();   // B(kh) visible; prior phase done with other buffer
        if (kh < 2) issueB(kh + 1, (kh + 1) & 1);

        const uint32_t bufbase = sb + SMB_OFF + (kh & 1) * SMB_BUF;
        const uint32_t aplaneH = sb + (rowsel + kh) * PLANE;
        const uint32_t aplaneL = aplaneH + 4 * PLANE;

#pragma unroll 1
        for (int kw = 0; kw < 3; ++kw) {
            const uint32_t btileH = bufbase + kw * 16384;
            const uint32_t btileL = btileH + 8192;
            const uint32_t arow = (uint32_t)(m0 + la_row + kw) * 128;
#pragma unroll
            for (int kt = 0; kt < 4; ++kt) {
                const uint32_t kcol = (uint32_t)(kt * 16 + la_k) * 2;
                const uint32_t bcol = (uint32_t)(kt * 16 + lb_k) * 2;
                uint32_t afh[4], afl[4];
                {
                    const uint32_t off = SWZ128(arow + kcol);
                    LDSM4(afh, aplaneH + off);
                    LDSM4(afl, aplaneL + off);
                }
                uint32_t bfh[4][4], bfl[4][4];
#pragma unroll
                for (int nt2 = 0; nt2 < 4; ++nt2) {
                    const uint32_t off = SWZ128((uint32_t)(nt2 * 16 + lb_n) * 128 + bcol);
                    LDSM4(bfh[nt2], btileH + off);
                    LDSM4(bfl[nt2], btileL + off);
                }
                // term-major: hh, lh, hl (same-acc reuse distance = 8 MMAs)
#pragma unroll
                for (int nt2 = 0; nt2 < 4; ++nt2) {
                    MMA_BF16(acc[nt2 * 2],     afh, bfh[nt2][0], bfh[nt2][1]);
                    MMA_BF16(acc[nt2 * 2 + 1], afh, bfh[nt2][2], bfh[nt2][3]);
                }
#pragma unroll
                for (int nt2 = 0; nt2 < 4; ++nt2) {
                    MMA_BF16(acc[nt2 * 2],     afl, bfh[nt2][0], bfh[nt2][1]);
                    MMA_BF16(acc[nt2 * 2 + 1], afl, bfh[nt2][2], bfh[nt2][3]);
                }
#pragma unroll
                for (int nt2 = 0; nt2 < 4; ++nt2) {
                    MMA_BF16(acc[nt2 * 2],     afh, bfl[nt2][0], bfl[nt2][1]);
                    MMA_BF16(acc[nt2 * 2 + 1], afh, bfl[nt2][2], bfl[nt2][3]);
                }
            }
        }
        // no trailing sync: next phase's top sync covers buffer-reuse safety
    }
    __syncthreads();   // all LDSM reads of A planes done before D aliases them

    // ---------- epilogue: acc -> smem D[2][64][132] -> gmem + IN partials ----
    float* D = (float*)smem;    // aliases A region
    {
        const int pr = lid >> 2, qc = 2 * (lid & 3);
#pragma unroll
        for (int nt = 0; nt < 8; ++nt) {
            const int opx = m0 + pr;
            const int co = nt * 8 + qc;
            float* dr = D + (size_t)(rowsel * 64 + co) * 132;
            dr[opx]            = acc[nt][0];
            dr[132 + opx]      = acc[nt][1];
            dr[opx + 8]        = acc[nt][2];
            dr[132 + opx + 8]  = acc[nt][3];
        }
    }
    __syncthreads();
    {   // coalesced store: 512 threads cover 128 (r,co)-rows x 128 px
        const int row = tid >> 2;            // 0..127 = r*64 + co
        const int r = row >> 6, co = row & 63;
        const int pxb = (tid & 3) * 32;
        float* op = dst + (size_t)b * CHW + (size_t)co * HWD + (y0 + r) * WW + pxb;
        const float* dr = D + (size_t)row * 132 + pxb;
#pragma unroll
        for (int i = 0; i < 8; ++i)
            *(float4*)(op + i * 4) = *(const float4*)(dr + i * 4);
    }
    {   // instance-norm partials: thread t -> (r, co, quarter)
        const int r = tid >> 8, co = (tid >> 2) & 63, q = tid & 3;
        const float* dr = D + (size_t)(r * 64 + co) * 132 + q * 32;
        float s = 0.f, s2 = 0.f;
#pragma unroll
        for (int i = 0; i < 32; ++i) { float v = dr[i]; s += v; s2 += v * v; }
        s  += __shfl_xor_sync(0xffffffffu, s, 1);
        s2 += __shfl_xor_sync(0xffffffffu, s2, 1);
        s  += __shfl_xor_sync(0xffffffffu, s, 2);
        s2 += __shfl_xor_sync(0xffffffffu, s2, 2);
        if (q == 0) {
            float* P = (float*)(smem + SM_PART);   // aliases B buf0 (done)
            P[r * 64 + co]       = s;
            P[128 + r * 64 + co] = s2;
        }
    }
    __syncthreads();
    if (tid < 64) {
        const float* P = (float*)(smem + SM_PART);
        const int g = b * 64 + tid;
        g_psum [g * 64 + rp] = P[tid] + P[64 + tid];
        g_psum2[g * 64 + rp] = P[128 + tid] + P[192 + tid];
    }
}

// ======================= stats reduce: 64 partials per group ============
__global__ void stats_reduce_kernel() {
    const int g = blockIdx.x;
    const int l = threadIdx.x;          // 32 threads
    float s  = g_psum [g * 64 + 2 * l] + g_psum [g * 64 + 2 * l + 1];
    float s2 = g_psum2[g * 64 + 2 * l] + g_psum2[g * 64 + 2 * l + 1];
#pragma unroll
    for (int o = 16; o; o >>= 1) {
        s  += __shfl_xor_sync(0xffffffffu, s, o);
        s2 += __shfl_xor_sync(0xffffffffu, s2, o);
    }
    if (l == 0) {
        const float inv = 1.f / (float)HWD;
        float m = s * inv;
        float var = s2 * inv - m * m;
        g_mean[g] = m;
        g_rstd[g] = rsqrtf(var + 1e-5f);
    }
}

__device__ __forceinline__ float lrelu(float v) { return v >= 0.f ? v : 0.2f * v; }

// ---------- out = lrelu(x + IN(buf2)) ----------
__global__ void final_kernel(const float* __restrict__ x, float* __restrict__ out) {
    const int i = blockIdx.x * 256 + threadIdx.x;      // float4 index
    float4 v  = ((const float4*)g_buf2)[i];
    float4 xv = ((const float4*)x)[i];
    const int g = i >> 12;
    const float m = g_mean[g], rs = g_rstd[g];
    float4 o;
    o.x = lrelu(xv.x + (v.x - m) * rs);
    o.y = lrelu(xv.y + (v.y - m) * rs);
    o.z = lrelu(xv.z + (v.z - m) * rs);
    o.w = lrelu(xv.w + (v.w - m) * rs);
    ((float4*)out)[i] = o;
}

extern "C" void kernel_launch(void* const* d_in, const int* in_sizes, int n_in,
                              void* d_out, int out_size) {
    const float* x  = (const float*)d_in[0];
    const float* k1 = (const float*)d_in[1];
    const float* k2 = (const float*)d_in[2];
    float* out = (float*)d_out;

    cudaFuncSetAttribute(conv_mma_kernel<0>, cudaFuncAttributeMaxDynamicSharedMemorySize, SMEM_TOTAL);
    cudaFuncSetAttribute(conv_mma_kernel<1>, cudaFuncAttributeMaxDynamicSharedMemorySize, SMEM_TOTAL);

    prep_w_kernel<<<(2 * WSZ + 255) / 256, 256>>>(k1, k2);

    dim3 grid(HH / 2, BB);   // (row-pair, batch)
    conv_mma_kernel<0><<<grid, NTHREADS, SMEM_TOTAL>>>(x);
    stats_reduce_kernel<<<NGRP, 32>>>();
    conv_mma_kernel<1><<<grid, NTHREADS, SMEM_TOTAL>>>(x);
    stats_reduce_kernel<<<NGRP, 32>>>();
    final_kernel<<<NELEM / 1024, 256>>>(x, out);
}

// round 11
// speedup vs baseline: 1.0940x; 1.0217x over previous
#include <cuda_runtime.h>
#include <cuda_bf16.h>
#include <cstdint>

#define BB 16
#define CC 64
#define HH 128
#define WW 128
#define HWD (HH*WW)            // 16384
#define CHW (CC*HWD)           // 1048576
#define NELEM (BB*CHW)         // 16777216
#define NGRP (BB*CC)           // 1024
#define WSZ (BB*CC*CC*9)       // 589824

// Scratch (device globals: allocation-free rule)
__device__ float g_buf1[NELEM];
__device__ float g_buf2[NELEM];
__device__ __align__(16) __nv_bfloat16 g_w1h[WSZ];
__device__ __align__(16) __nv_bfloat16 g_w1l[WSZ];
__device__ __align__(16) __nv_bfloat16 g_w2h[WSZ];
__device__ __align__(16) __nv_bfloat16 g_w2l[WSZ];
__device__ float g_mean[NGRP];
__device__ float g_rstd[NGRP];
__device__ float g_psum[NGRP * 64];    // [group][rowpair]
__device__ float g_psum2[NGRP * 64];

// ======================= PTX helpers (plain compute_103-safe) ==========
__device__ __forceinline__ uint32_t smem_u32(const void* p) {
    uint32_t a;
    asm("{ .reg .u64 t; cvta.to.shared.u64 t, %1; cvt.u32.u64 %0, t; }" : "=r"(a) : "l"(p));
    return a;
}
#define STS128(r0, r1, r2, r3, addr) \
    asm volatile("st.shared.v4.b32 [%0], {%1, %2, %3, %4};" \
        :: "r"(addr), "r"(r0), "r"(r1), "r"(r2), "r"(r3) : "memory")
#define LDSM4(r, addr) \
    asm volatile("ldmatrix.sync.aligned.m8n8.x4.shared.b16 {%0,%1,%2,%3}, [%4];" \
        : "=r"((r)[0]), "=r"((r)[1]), "=r"((r)[2]), "=r"((r)[3]) : "r"(addr))
#define MMA_BF16(d, a, b0, b1) \
    asm volatile("mma.sync.aligned.m16n8k16.row.col.f32.bf16.bf16.f32 " \
        "{%0,%1,%2,%3}, {%4,%5,%6,%7}, {%8,%9}, {%0,%1,%2,%3};" \
        : "+f"((d)[0]), "+f"((d)[1]), "+f"((d)[2]), "+f"((d)[3]) \
        : "r"((a)[0]), "r"((a)[1]), "r"((a)[2]), "r"((a)[3]), "r"(b0), "r"(b1))
#define CP_ASYNC16(dst, src) \
    asm volatile("cp.async.cg.shared.global [%0], [%1], 16;" :: "r"(dst), "l"(src) : "memory")
#define CP_COMMIT() asm volatile("cp.async.commit_group;" ::: "memory")
#define CP_WAIT(n)  asm volatile("cp.async.wait_group %0;" :: "n"(n) : "memory")
#define SWZ128(off) ((uint32_t)(off) ^ ((((uint32_t)(off)) >> 3) & 0x70u))

// ---- dynamic smem layout (bytes) ----
// A: [part(2)][krow(4)] planes of 130 px x 64 ci bf16, stride 16640
// B: 2 buffers of [kw(3)][part(2)] tiles 64co x 64ci bf16 (8192 B each) = 48 KB
// stats alias start of B buf1 (prologue-only); partials alias B buf0 (epilogue-only)
#define PLANE 16640
#define SMB_OFF (8 * PLANE)              // 133120
#define SMB_BUF 49152
#define SM_STAT (SMB_OFF + SMB_BUF)      // buf1 start (prologue-only use)
#define SM_PART (SMB_OFF)                // buf0 start (epilogue-only use)
#define SMEM_TOTAL (SMB_OFF + 2 * SMB_BUF)   // 231424 (< 227 KB cap = 232448)

#define NTHREADS 512

// ======================= weight prep: fp32 -> split bf16 ================
// dst layout: [b][tap(kh*3+kw)][co][ci]
__global__ void prep_w_kernel(const float* __restrict__ k1, const float* __restrict__ k2) {
    int gi = blockIdx.x * 256 + threadIdx.x;
    if (gi >= 2 * WSZ) return;
    const float* src; __nv_bfloat16 *dh, *dl; int i;
    if (gi < WSZ) { src = k1; dh = g_w1h; dl = g_w1l; i = gi; }
    else          { src = k2; dh = g_w2h; dl = g_w2l; i = gi - WSZ; }
    int ci = i & 63;
    int co = (i >> 6) & 63;
    int k9 = (i >> 12) % 9;
    int b  = (i >> 12) / 9;
    float w = src[(((b * 64 + co) * 64 + ci) * 9) + k9];
    __nv_bfloat16 h = __float2bfloat16(w);
    __nv_bfloat16 l = __float2bfloat16(w - __bfloat162float(h));
    dh[i] = h; dl[i] = l;
}

// ======================= conv via mma.sync bf16 split ===================
// CTA = (row-pair, batch), 512 threads = 16 warps (4/SMSP).
// Warp tile 32px x 32co: 16 warps = 2 rows x 4 Mtiles x 2 Ntiles.
// Per (kw,kt): 8 LDSM feed 24 MMAs (best smem-read economy at this occupancy).
template<int PASS>
__global__ __launch_bounds__(NTHREADS, 1)
void conv_mma_kernel(const float* __restrict__ x_ext) {
    extern __shared__ __align__(1024) char smem[];
    const uint32_t sb = smem_u32(smem);
    const int tid = threadIdx.x, lid = tid & 31, wid = tid >> 5;
    const int rp = blockIdx.x, y0 = rp * 2, b = blockIdx.y;
    const float* src = (PASS == 0) ? x_ext : g_buf1;
    const __nv_bfloat16* wh = (PASS == 0) ? g_w1h : g_w2h;
    const __nv_bfloat16* wl = (PASS == 0) ? g_w1l : g_w2l;
    float* dst = (PASS == 0) ? g_buf1 : g_buf2;

    float* smean = (float*)(smem + SM_STAT);   // aliases B buf1 (prologue only)
    float* srstd = smean + 64;

    if (PASS == 1) {
        if (tid < 64) {
            smean[tid] = g_mean[b * 64 + tid];
            srstd[tid] = g_rstd[b * 64 + tid];
        }
        __syncthreads();
    }

    // ---- B stage issue: both parts, all 3 kw (48 KB) into buffer buf ----
    auto issueB = [&](int kh, int buf) {
#pragma unroll
        for (int kw = 0; kw < 3; ++kw) {
#pragma unroll
            for (int part = 0; part < 2; ++part) {
                const __nv_bfloat16* s = (part ? wl : wh)
                    + (size_t)(b * 9 + kh * 3 + kw) * 4096;
                const uint32_t dstb = sb + SMB_OFF + buf * SMB_BUF
                                    + kw * 16384 + part * 8192;
                CP_ASYNC16(dstb + SWZ128(tid * 16), s + tid * 8);
            }
        }
        CP_COMMIT();
    };

    // prologue: B(0) in flight while A stages
    issueB(0, 0);

    // ---------- stage A: 4 kh-rows x 130 px x 64 ci, hi+lo ----------
    // hi = truncated top-16 bits (PRMT); lo = rn(f - hi) via bf16x2 cvt.
    {
        const int px = tid & 127;
        const int cihalf = (tid >> 7) * 16;
        const int ar = px + 1;
#pragma unroll
        for (int krow = 0; krow < 4; ++krow) {
            const int grow = y0 + krow - 1;
            const bool vr = (unsigned)grow < 128u;
            const float* base = src + (size_t)b * CHW + (size_t)(vr ? grow : 0) * WW + px;
            const uint32_t ph = sb + (0 * 4 + krow) * PLANE;
            const uint32_t pl = sb + (1 * 4 + krow) * PLANE;
#pragma unroll
            for (int c8 = 0; c8 < 2; ++c8) {
                const int ci0 = cihalf + c8 * 8;
                float v[8];
#pragma unroll
                for (int j = 0; j < 8; ++j) {
                    float t = vr ? __ldg(base + (size_t)(ci0 + j) * HWD) : 0.f;
                    if (PASS == 1 && vr) {
                        t = (t - smean[ci0 + j]) * srstd[ci0 + j];
                        t = t >= 0.f ? t : 0.2f * t;
                    }
                    v[j] = t;
                }
                uint32_t hp[4], lp[4];
#pragma unroll
                for (int j = 0; j < 4; ++j) {
                    const uint32_t u0 = __float_as_uint(v[2*j]);
                    const uint32_t u1 = __float_as_uint(v[2*j+1]);
                    hp[j] = __byte_perm(u0, u1, 0x7632);   // {hi16(u0), hi16(u1)}
                    const float h0 = __uint_as_float(u0 & 0xFFFF0000u);
                    const float h1 = __uint_as_float(u1 & 0xFFFF0000u);
                    asm("cvt.rn.bf16x2.f32 %0, %1, %2;"
                        : "=r"(lp[j]) : "f"(v[2*j+1] - h1), "f"(v[2*j] - h0));
                }
                const uint32_t off = SWZ128(ar * 128 + ci0 * 2);
                STS128(hp[0], hp[1], hp[2], hp[3], ph + off);
                STS128(lp[0], lp[1], lp[2], lp[3], pl + off);
            }
        }
        if (tid < 128) {   // zero halo rows ar=0 / ar=129, all 8 planes
            const int plane = tid >> 4;
            const int row = (tid & 8) ? 129 : 0;
            const int chunk = tid & 7;
            STS128(0u, 0u, 0u, 0u, sb + plane * PLANE + SWZ128(row * 128 + chunk * 16));
        }
    }

    // ---------- warp tiling: 2 rows x 4 Mtiles(32px) x 2 Ntiles(32co) ----------
    const int rowsel = wid >> 3;
    const int m0 = ((wid >> 1) & 3) * 32;
    const int n0 = (wid & 1) * 32;
    const int la_row = lid & 15;
    const int la_k   = (lid & 16) ? 8 : 0;
    const int lb_n   = (lid & 7) + ((lid & 16) ? 8 : 0);
    const int lb_k   = (lid & 8);

    float acc[2][4][4];
#pragma unroll
    for (int mt = 0; mt < 2; ++mt)
#pragma unroll
        for (int nt = 0; nt < 4; ++nt)
#pragma unroll
            for (int j = 0; j < 4; ++j) acc[mt][nt][j] = 0.f;

#pragma unroll 1
    for (int kh = 0; kh < 3; ++kh) {
        CP_WAIT(0);
        __syncthreads();   // B(kh) visible; prior phase done with other buffer
        if (kh < 2) issueB(kh + 1, (kh + 1) & 1);

        const uint32_t bufbase = sb + SMB_OFF + (kh & 1) * SMB_BUF;
        const uint32_t aplaneH = sb + (rowsel + kh) * PLANE;
        const uint32_t aplaneL = aplaneH + 4 * PLANE;

#pragma unroll 1
        for (int kw = 0; kw < 3; ++kw) {
            const uint32_t btileH = bufbase + kw * 16384;
            const uint32_t btileL = btileH + 8192;
            const uint32_t arow = (uint32_t)(m0 + la_row + kw) * 128;
#pragma unroll
            for (int kt = 0; kt < 4; ++kt) {
                const uint32_t kcol = (uint32_t)(kt * 16 + la_k) * 2;
                const uint32_t bcol = (uint32_t)(kt * 16 + lb_k) * 2;
                uint32_t afh[2][4], afl[2][4];
#pragma unroll
                for (int mt = 0; mt < 2; ++mt) {
                    const uint32_t off = SWZ128(arow + (uint32_t)(mt * 16) * 128 + kcol);
                    LDSM4(afh[mt], aplaneH + off);
                    LDSM4(afl[mt], aplaneL + off);
                }
                uint32_t bfh[2][4], bfl[2][4];
#pragma unroll
                for (int nt2 = 0; nt2 < 2; ++nt2) {
                    const uint32_t off = SWZ128((uint32_t)(n0 + nt2 * 16 + lb_n) * 128 + bcol);
                    LDSM4(bfh[nt2], btileH + off);
                    LDSM4(bfl[nt2], btileL + off);
                }
                // term-major: hh, lh, hl
#pragma unroll
                for (int mt = 0; mt < 2; ++mt)
#pragma unroll
                    for (int nt2 = 0; nt2 < 2; ++nt2) {
                        MMA_BF16(acc[mt][nt2 * 2],     afh[mt], bfh[nt2][0], bfh[nt2][1]);
                        MMA_BF16(acc[mt][nt2 * 2 + 1], afh[mt], bfh[nt2][2], bfh[nt2][3]);
                    }
#pragma unroll
                for (int mt = 0; mt < 2; ++mt)
#pragma unroll
                    for (int nt2 = 0; nt2 < 2; ++nt2) {
                        MMA_BF16(acc[mt][nt2 * 2],     afl[mt], bfh[nt2][0], bfh[nt2][1]);
                        MMA_BF16(acc[mt][nt2 * 2 + 1], afl[mt], bfh[nt2][2], bfh[nt2][3]);
                    }
#pragma unroll
                for (int mt = 0; mt < 2; ++mt)
#pragma unroll
                    for (int nt2 = 0; nt2 < 2; ++nt2) {
                        MMA_BF16(acc[mt][nt2 * 2],     afh[mt], bfl[nt2][0], bfl[nt2][1]);
                        MMA_BF16(acc[mt][nt2 * 2 + 1], afh[mt], bfl[nt2][2], bfl[nt2][3]);
                    }
            }
        }
        // no trailing sync: next phase's top sync covers buffer-reuse safety
    }
    __syncthreads();   // all LDSM reads of A planes done before D aliases them

    // ---------- epilogue: acc -> smem D[2][64][132] -> gmem + IN partials ----
    float* D = (float*)smem;    // aliases A region
    {
        const int pr = lid >> 2, qc = 2 * (lid & 3);
#pragma unroll
        for (int mt = 0; mt < 2; ++mt) {
#pragma unroll
            for (int nt = 0; nt < 4; ++nt) {
                const int opx = m0 + mt * 16 + pr;
                const int co = n0 + nt * 8 + qc;
                float* dr = D + (size_t)(rowsel * 64 + co) * 132;
                dr[opx]            = acc[mt][nt][0];
                dr[132 + opx]      = acc[mt][nt][1];
                dr[opx + 8]        = acc[mt][nt][2];
                dr[132 + opx + 8]  = acc[mt][nt][3];
            }
        }
    }
    __syncthreads();
    {   // coalesced store: 512 threads cover 128 (r,co)-rows x 128 px
        const int row = tid >> 2;            // 0..127 = r*64 + co
        const int r = row >> 6, co = row & 63;
        const int pxb = (tid & 3) * 32;
        float* op = dst + (size_t)b * CHW + (size_t)co * HWD + (y0 + r) * WW + pxb;
        const float* dr = D + (size_t)row * 132 + pxb;
#pragma unroll
        for (int i = 0; i < 8; ++i)
            *(float4*)(op + i * 4) = *(const float4*)(dr + i * 4);
    }
    {   // instance-norm partials: thread t -> (r, co, quarter)
        const int r = tid >> 8, co = (tid >> 2) & 63, q = tid & 3;
        const float* dr = D + (size_t)(r * 64 + co) * 132 + q * 32;
        float s = 0.f, s2 = 0.f;
#pragma unroll
        for (int i = 0; i < 32; ++i) { float v = dr[i]; s += v; s2 += v * v; }
        s  += __shfl_xor_sync(0xffffffffu, s, 1);
        s2 += __shfl_xor_sync(0xffffffffu, s2, 1);
        s  += __shfl_xor_sync(0xffffffffu, s, 2);
        s2 += __shfl_xor_sync(0xffffffffu, s2, 2);
        if (q == 0) {
            float* P = (float*)(smem + SM_PART);   // aliases B buf0 (done)
            P[r * 64 + co]       = s;
            P[128 + r * 64 + co] = s2;
        }
    }
    __syncthreads();
    if (tid < 64) {
        const float* P = (float*)(smem + SM_PART);
        const int g = b * 64 + tid;
        g_psum [g * 64 + rp] = P[tid] + P[64 + tid];
        g_psum2[g * 64 + rp] = P[128 + tid] + P[192 + tid];
    }
}

// ======================= stats reduce: 64 partials per group ============
__global__ void stats_reduce_kernel() {
    const int g = blockIdx.x;
    const int l = threadIdx.x;          // 32 threads
    float s  = g_psum [g * 64 + 2 * l] + g_psum [g * 64 + 2 * l + 1];
    float s2 = g_psum2[g * 64 + 2 * l] + g_psum2[g * 64 + 2 * l + 1];
#pragma unroll
    for (int o = 16; o; o >>= 1) {
        s  += __shfl_xor_sync(0xffffffffu, s, o);
        s2 += __shfl_xor_sync(0xffffffffu, s2, o);
    }
    if (l == 0) {
        const float inv = 1.f / (float)HWD;
        float m = s * inv;
        float var = s2 * inv - m * m;
        g_mean[g] = m;
        g_rstd[g] = rsqrtf(var + 1e-5f);
    }
}

__device__ __forceinline__ float lrelu(float v) { return v >= 0.f ? v : 0.2f * v; }

// ---------- out = lrelu(x + IN(buf2)) ----------
__global__ void final_kernel(const float* __restrict__ x, float* __restrict__ out) {
    const int i = blockIdx.x * 256 + threadIdx.x;      // float4 index
    float4 v  = ((const float4*)g_buf2)[i];
    float4 xv = ((const float4*)x)[i];
    const int g = i >> 12;
    const float m = g_mean[g], rs = g_rstd[g];
    float4 o;
    o.x = lrelu(xv.x + (v.x - m) * rs);
    o.y = lrelu(xv.y + (v.y - m) * rs);
    o.z = lrelu(xv.z + (v.z - m) * rs);
    o.w = lrelu(xv.w + (v.w - m) * rs);
    ((float4*)out)[i] = o;
}

extern "C" void kernel_launch(void* const* d_in, const int* in_sizes, int n_in,
                              void* d_out, int out_size) {
    const float* x  = (const float*)d_in[0];
    const float* k1 = (const float*)d_in[1];
    const float* k2 = (const float*)d_in[2];
    float* out = (float*)d_out;

    cudaFuncSetAttribute(conv_mma_kernel<0>, cudaFuncAttributeMaxDynamicSharedMemorySize, SMEM_TOTAL);
    cudaFuncSetAttribute(conv_mma_kernel<1>, cudaFuncAttributeMaxDynamicSharedMemorySize, SMEM_TOTAL);

    prep_w_kernel<<<(2 * WSZ + 255) / 256, 256>>>(k1, k2);

    dim3 grid(HH / 2, BB);   // (row-pair, batch)
    conv_mma_kernel<0><<<grid, NTHREADS, SMEM_TOTAL>>>(x);
    stats_reduce_kernel<<<NGRP, 32>>>();
    conv_mma_kernel<1><<<grid, NTHREADS, SMEM_TOTAL>>>(x);
    stats_reduce_kernel<<<NGRP, 32>>>();
    final_kernel<<<NELEM / 1024, 256>>>(x, out);
}

// round 12
// speedup vs baseline: 1.3773x; 1.2589x over previous
#include <cuda_runtime.h>
#include <cuda_fp16.h>
#include <cstdint>

#define BB 16
#define CC 64
#define HH 128
#define WW 128
#define HWD (HH*WW)            // 16384
#define CHW (CC*HWD)           // 1048576
#define NELEM (BB*CHW)         // 16777216
#define NGRP (BB*CC)           // 1024
#define WSZ (BB*CC*CC*9)       // 589824

// Scratch (device globals: allocation-free rule)
__device__ float g_buf1[NELEM];
__device__ float g_buf2[NELEM];
__device__ __align__(16) __half g_w1h[WSZ];
__device__ __align__(16) __half g_w2h[WSZ];
__device__ float g_mean[NGRP];
__device__ float g_rstd[NGRP];
__device__ float g_psum[NGRP * 64];    // [group][rowpair]
__device__ float g_psum2[NGRP * 64];

// ======================= PTX helpers (plain compute_103-safe) ==========
__device__ __forceinline__ uint32_t smem_u32(const void* p) {
    uint32_t a;
    asm("{ .reg .u64 t; cvta.to.shared.u64 t, %1; cvt.u32.u64 %0, t; }" : "=r"(a) : "l"(p));
    return a;
}
#define STS128(r0, r1, r2, r3, addr) \
    asm volatile("st.shared.v4.b32 [%0], {%1, %2, %3, %4};" \
        :: "r"(addr), "r"(r0), "r"(r1), "r"(r2), "r"(r3) : "memory")
#define LDSM4(r, addr) \
    asm volatile("ldmatrix.sync.aligned.m8n8.x4.shared.b16 {%0,%1,%2,%3}, [%4];" \
        : "=r"((r)[0]), "=r"((r)[1]), "=r"((r)[2]), "=r"((r)[3]) : "r"(addr))
#define MMA_F16(d, a, b0, b1) \
    asm volatile("mma.sync.aligned.m16n8k16.row.col.f32.f16.f16.f32 " \
        "{%0,%1,%2,%3}, {%4,%5,%6,%7}, {%8,%9}, {%0,%1,%2,%3};" \
        : "+f"((d)[0]), "+f"((d)[1]), "+f"((d)[2]), "+f"((d)[3]) \
        : "r"((a)[0]), "r"((a)[1]), "r"((a)[2]), "r"((a)[3]), "r"(b0), "r"(b1))
#define CP_ASYNC16(dst, src) \
    asm volatile("cp.async.cg.shared.global [%0], [%1], 16;" :: "r"(dst), "l"(src) : "memory")
#define CP_COMMIT() asm volatile("cp.async.commit_group;" ::: "memory")
#define CP_WAIT(n)  asm volatile("cp.async.wait_group %0;" :: "n"(n) : "memory")
#define SWZ128(off) ((uint32_t)(off) ^ ((((uint32_t)(off)) >> 3) & 0x70u))

// ---- dynamic smem layout (bytes) ----
// A: [part(2)][krow(4)] planes of 130 px x 64 ci fp16, stride 16640
//    (part 0 = hi fp16, part 1 = lo residual fp16; A exact to ~2^-22)
// B: 2 buffers of [kw(3)] tiles 64co x 64ci fp16 (8192 B each) = 24 KB/buf
// stats alias start of B buf1 (prologue-only); partials alias B buf0 (epilogue-only)
#define PLANE 16640
#define SMB_OFF (8 * PLANE)              // 133120
#define SMB_BUF 24576
#define SM_STAT (SMB_OFF + SMB_BUF)      // buf1 start (prologue-only use)
#define SM_PART (SMB_OFF)                // buf0 start (epilogue-only use)
#define SMEM_TOTAL (SMB_OFF + 2 * SMB_BUF)   // 182272 (< 227 KB cap)

#define NTHREADS 512

// ======================= weight prep: fp32 -> fp16 (rn), transposed ====
// dst layout: [b][tap(kh*3+kw)][co][ci]
__global__ void prep_w_kernel(const float* __restrict__ k1, const float* __restrict__ k2) {
    int gi = blockIdx.x * 256 + threadIdx.x;
    if (gi >= 2 * WSZ) return;
    const float* src; __half* dh; int i;
    if (gi < WSZ) { src = k1; dh = g_w1h; i = gi; }
    else          { src = k2; dh = g_w2h; i = gi - WSZ; }
    int ci = i & 63;
    int co = (i >> 6) & 63;
    int k9 = (i >> 12) % 9;
    int b  = (i >> 12) / 9;
    dh[i] = __float2half_rn(src[(((b * 64 + co) * 64 + ci) * 9) + k9]);
}

// ======================= conv via mma.sync fp16 2-term ==================
// CTA = (row-pair, batch), 512 threads = 16 warps (4/SMSP).
// Warp tile 32px x 32co: 16 warps = 2 rows x 4 Mtiles x 2 Ntiles.
// A split fp16 hi+lo (exact to 2^-22); B plain fp16 (error 2^-11 -> ~3e-4 L2).
// Per (kw,kt): 6 LDSM feed 16 MMAs (2 terms: Ah*B, Al*B).
template<int PASS>
__global__ __launch_bounds__(NTHREADS, 1)
void conv_mma_kernel(const float* __restrict__ x_ext) {
    extern __shared__ __align__(1024) char smem[];
    const uint32_t sb = smem_u32(smem);
    const int tid = threadIdx.x, lid = tid & 31, wid = tid >> 5;
    const int rp = blockIdx.x, y0 = rp * 2, b = blockIdx.y;
    const float* src = (PASS == 0) ? x_ext : g_buf1;
    const __half* wh = (PASS == 0) ? g_w1h : g_w2h;
    float* dst = (PASS == 0) ? g_buf1 : g_buf2;

    float* smean = (float*)(smem + SM_STAT);   // aliases B buf1 (prologue only)
    float* srstd = smean + 64;

    if (PASS == 1) {
        if (tid < 64) {
            smean[tid] = g_mean[b * 64 + tid];
            srstd[tid] = g_rstd[b * 64 + tid];
        }
        __syncthreads();
    }

    // ---- B stage issue: all 3 kw (24 KB) into buffer buf ----
    auto issueB = [&](int kh, int buf) {
#pragma unroll
        for (int kw = 0; kw < 3; ++kw) {
            const __half* s = wh + (size_t)(b * 9 + kh * 3 + kw) * 4096;
            const uint32_t dstb = sb + SMB_OFF + buf * SMB_BUF + kw * 8192;
            CP_ASYNC16(dstb + SWZ128(tid * 16), s + tid * 8);
        }
        CP_COMMIT();
    };

    // prologue: B(0) in flight while A stages
    issueB(0, 0);

    // ---------- stage A: 4 kh-rows x 130 px x 64 ci, fp16 hi+lo ----------
    {
        const int px = tid & 127;
        const int cihalf = (tid >> 7) * 16;
        const int ar = px + 1;
#pragma unroll
        for (int krow = 0; krow < 4; ++krow) {
            const int grow = y0 + krow - 1;
            const bool vr = (unsigned)grow < 128u;
            const float* base = src + (size_t)b * CHW + (size_t)(vr ? grow : 0) * WW + px;
            const uint32_t ph = sb + (0 * 4 + krow) * PLANE;
            const uint32_t pl = sb + (1 * 4 + krow) * PLANE;
#pragma unroll
            for (int c8 = 0; c8 < 2; ++c8) {
                const int ci0 = cihalf + c8 * 8;
                float v[8];
#pragma unroll
                for (int j = 0; j < 8; ++j) {
                    float t = vr ? __ldg(base + (size_t)(ci0 + j) * HWD) : 0.f;
                    if (PASS == 1 && vr) {
                        t = (t - smean[ci0 + j]) * srstd[ci0 + j];
                        t = t >= 0.f ? t : 0.2f * t;
                    }
                    v[j] = t;
                }
                uint32_t hp[4], lp[4];
#pragma unroll
                for (int j = 0; j < 4; ++j) {
                    __half2 h2 = __floats2half2_rn(v[2*j], v[2*j+1]);
                    float2 hf = __half22float2(h2);
                    __half2 l2 = __floats2half2_rn(v[2*j] - hf.x, v[2*j+1] - hf.y);
                    hp[j] = *(uint32_t*)&h2;
                    lp[j] = *(uint32_t*)&l2;
                }
                const uint32_t off = SWZ128(ar * 128 + ci0 * 2);
                STS128(hp[0], hp[1], hp[2], hp[3], ph + off);
                STS128(lp[0], lp[1], lp[2], lp[3], pl + off);
            }
        }
        if (tid < 128) {   // zero halo rows ar=0 / ar=129, all 8 planes
            const int plane = tid >> 4;
            const int row = (tid & 8) ? 129 : 0;
            const int chunk = tid & 7;
            STS128(0u, 0u, 0u, 0u, sb + plane * PLANE + SWZ128(row * 128 + chunk * 16));
        }
    }

    // ---------- warp tiling: 2 rows x 4 Mtiles(32px) x 2 Ntiles(32co) ----------
    const int rowsel = wid >> 3;
    const int m0 = ((wid >> 1) & 3) * 32;
    const int n0 = (wid & 1) * 32;
    const int la_row = lid & 15;
    const int la_k   = (lid & 16) ? 8 : 0;
    const int lb_n   = (lid & 7) + ((lid & 16) ? 8 : 0);
    const int lb_k   = (lid & 8);

    float acc[2][4][4];
#pragma unroll
    for (int mt = 0; mt < 2; ++mt)
#pragma unroll
        for (int nt = 0; nt < 4; ++nt)
#pragma unroll
            for (int j = 0; j < 4; ++j) acc[mt][nt][j] = 0.f;

#pragma unroll 1
    for (int kh = 0; kh < 3; ++kh) {
        CP_WAIT(0);
        __syncthreads();   // B(kh) visible; prior phase done with other buffer
        if (kh < 2) issueB(kh + 1, (kh + 1) & 1);

        const uint32_t bufbase = sb + SMB_OFF + (kh & 1) * SMB_BUF;
        const uint32_t aplaneH = sb + (rowsel + kh) * PLANE;
        const uint32_t aplaneL = aplaneH + 4 * PLANE;

#pragma unroll 1
        for (int kw = 0; kw < 3; ++kw) {
            const uint32_t btile = bufbase + kw * 8192;
            const uint32_t arow = (uint32_t)(m0 + la_row + kw) * 128;
#pragma unroll
            for (int kt = 0; kt < 4; ++kt) {
                const uint32_t kcol = (uint32_t)(kt * 16 + la_k) * 2;
                const uint32_t bcol = (uint32_t)(kt * 16 + lb_k) * 2;
                uint32_t afh[2][4], afl[2][4];
#pragma unroll
                for (int mt = 0; mt < 2; ++mt) {
                    const uint32_t off = SWZ128(arow + (uint32_t)(mt * 16) * 128 + kcol);
                    LDSM4(afh[mt], aplaneH + off);
                    LDSM4(afl[mt], aplaneL + off);
                }
                uint32_t bf[2][4];
#pragma unroll
                for (int nt2 = 0; nt2 < 2; ++nt2) {
                    const uint32_t off = SWZ128((uint32_t)(n0 + nt2 * 16 + lb_n) * 128 + bcol);
                    LDSM4(bf[nt2], btile + off);
                }
                // term-major: Ah*B then Al*B (acc reuse distance = 8 MMAs)
#pragma unroll
                for (int mt = 0; mt < 2; ++mt)
#pragma unroll
                    for (int nt2 = 0; nt2 < 2; ++nt2) {
                        MMA_F16(acc[mt][nt2 * 2],     afh[mt], bf[nt2][0], bf[nt2][1]);
                        MMA_F16(acc[mt][nt2 * 2 + 1], afh[mt], bf[nt2][2], bf[nt2][3]);
                    }
#pragma unroll
                for (int mt = 0; mt < 2; ++mt)
#pragma unroll
                    for (int nt2 = 0; nt2 < 2; ++nt2) {
                        MMA_F16(acc[mt][nt2 * 2],     afl[mt], bf[nt2][0], bf[nt2][1]);
                        MMA_F16(acc[mt][nt2 * 2 + 1], afl[mt], bf[nt2][2], bf[nt2][3]);
                    }
            }
        }
        // no trailing sync: next phase's top sync covers buffer-reuse safety
    }
    __syncthreads();   // all LDSM reads of A planes done before D aliases them

    // ---------- epilogue: acc -> smem D[2][64][132] -> gmem + IN partials ----
    float* D = (float*)smem;    // aliases A region
    {
        const int pr = lid >> 2, qc = 2 * (lid & 3);
#pragma unroll
        for (int mt = 0; mt < 2; ++mt) {
#pragma unroll
            for (int nt = 0; nt < 4; ++nt) {
                const int opx = m0 + mt * 16 + pr;
                const int co = n0 + nt * 8 + qc;
                float* dr = D + (size_t)(rowsel * 64 + co) * 132;
                dr[opx]            = acc[mt][nt][0];
                dr[132 + opx]      = acc[mt][nt][1];
                dr[opx + 8]        = acc[mt][nt][2];
                dr[132 + opx + 8]  = acc[mt][nt][3];
            }
        }
    }
    __syncthreads();
    {   // coalesced store: 512 threads cover 128 (r,co)-rows x 128 px
        const int row = tid >> 2;            // 0..127 = r*64 + co
        const int r = row >> 6, co = row & 63;
        const int pxb = (tid & 3) * 32;
        float* op = dst + (size_t)b * CHW + (size_t)co * HWD + (y0 + r) * WW + pxb;
        const float* dr = D + (size_t)row * 132 + pxb;
#pragma unroll
        for (int i = 0; i < 8; ++i)
            *(float4*)(op + i * 4) = *(const float4*)(dr + i * 4);
    }
    {   // instance-norm partials: thread t -> (r, co, quarter)
        const int r = tid >> 8, co = (tid >> 2) & 63, q = tid & 3;
        const float* dr = D + (size_t)(r * 64 + co) * 132 + q * 32;
        float s = 0.f, s2 = 0.f;
#pragma unroll
        for (int i = 0; i < 32; ++i) { float v = dr[i]; s += v; s2 += v * v; }
        s  += __shfl_xor_sync(0xffffffffu, s, 1);
        s2 += __shfl_xor_sync(0xffffffffu, s2, 1);
        s  += __shfl_xor_sync(0xffffffffu, s, 2);
        s2 += __shfl_xor_sync(0xffffffffu, s2, 2);
        if (q == 0) {
            float* P = (float*)(smem + SM_PART);   // aliases B buf0 (done)
            P[r * 64 + co]       = s;
            P[128 + r * 64 + co] = s2;
        }
    }
    __syncthreads();
    if (tid < 64) {
        const float* P = (float*)(smem + SM_PART);
        const int g = b * 64 + tid;
        g_psum [g * 64 + rp] = P[tid] + P[64 + tid];
        g_psum2[g * 64 + rp] = P[128 + tid] + P[192 + tid];
    }
}

// ======================= stats reduce: 64 partials per group ============
__global__ void stats_reduce_kernel() {
    const int g = blockIdx.x;
    const int l = threadIdx.x;          // 32 threads
    float s  = g_psum [g * 64 + 2 * l] + g_psum [g * 64 + 2 * l + 1];
    float s2 = g_psum2[g * 64 + 2 * l] + g_psum2[g * 64 + 2 * l + 1];
#pragma unroll
    for (int o = 16; o; o >>= 1) {
        s  += __shfl_xor_sync(0xffffffffu, s, o);
        s2 += __shfl_xor_sync(0xffffffffu, s2, o);
    }
    if (l == 0) {
        const float inv = 1.f / (float)HWD;
        float m = s * inv;
        float var = s2 * inv - m * m;
        g_mean[g] = m;
        g_rstd[g] = rsqrtf(var + 1e-5f);
    }
}

__device__ __forceinline__ float lrelu(float v) { return v >= 0.f ? v : 0.2f * v; }

// ---------- out = lrelu(x + IN(buf2)) ----------
__global__ void final_kernel(const float* __restrict__ x, float* __restrict__ out) {
    const int i = blockIdx.x * 256 + threadIdx.x;      // float4 index
    float4 v  = ((const float4*)g_buf2)[i];
    float4 xv = ((const float4*)x)[i];
    const int g = i >> 12;
    const float m = g_mean[g], rs = g_rstd[g];
    float4 o;
    o.x = lrelu(xv.x + (v.x - m) * rs);
    o.y = lrelu(xv.y + (v.y - m) * rs);
    o.z = lrelu(xv.z + (v.z - m) * rs);
    o.w = lrelu(xv.w + (v.w - m) * rs);
    ((float4*)out)[i] = o;
}

extern "C" void kernel_launch(void* const* d_in, const int* in_sizes, int n_in,
                              void* d_out, int out_size) {
    const float* x  = (const float*)d_in[0];
    const float* k1 = (const float*)d_in[1];
    const float* k2 = (const float*)d_in[2];
    float* out = (float*)d_out;

    cudaFuncSetAttribute(conv_mma_kernel<0>, cudaFuncAttributeMaxDynamicSharedMemorySize, SMEM_TOTAL);
    cudaFuncSetAttribute(conv_mma_kernel<1>, cudaFuncAttributeMaxDynamicSharedMemorySize, SMEM_TOTAL);

    prep_w_kernel<<<(2 * WSZ + 255) / 256, 256>>>(k1, k2);

    dim3 grid(HH / 2, BB);   // (row-pair, batch)
    conv_mma_kernel<0><<<grid, NTHREADS, SMEM_TOTAL>>>(x);
    stats_reduce_kernel<<<NGRP, 32>>>();
    conv_mma_kernel<1><<<grid, NTHREADS, SMEM_TOTAL>>>(x);
    stats_reduce_kernel<<<NGRP, 32>>>();
    final_kernel<<<NELEM / 1024, 256>>>(x, out);
}

// round 13
// speedup vs baseline: 1.7577x; 1.2762x over previous
#include <cuda_runtime.h>
#include <cuda_fp16.h>
#include <cstdint>

#define BB 16
#define CC 64
#define HH 128
#define WW 128
#define HWD (HH*WW)            // 16384
#define CHW (CC*HWD)           // 1048576
#define NELEM (BB*CHW)         // 16777216
#define NGRP (BB*CC)           // 1024
#define WSZ (BB*CC*CC*9)       // 589824

// Scratch (device globals: allocation-free rule)
__device__ float g_buf1[NELEM];
__device__ float g_buf2[NELEM];
__device__ __align__(16) __half g_w1h[WSZ];
__device__ __align__(16) __half g_w2h[WSZ];
__device__ float g_mean[NGRP];
__device__ float g_rstd[NGRP];
__device__ float g_psum[NGRP * 64];    // [group][rowpair]
__device__ float g_psum2[NGRP * 64];

// ======================= PTX helpers (plain compute_103-safe) ==========
__device__ __forceinline__ uint32_t smem_u32(const void* p) {
    uint32_t a;
    asm("{ .reg .u64 t; cvta.to.shared.u64 t, %1; cvt.u32.u64 %0, t; }" : "=r"(a) : "l"(p));
    return a;
}
#define STS128(r0, r1, r2, r3, addr) \
    asm volatile("st.shared.v4.b32 [%0], {%1, %2, %3, %4};" \
        :: "r"(addr), "r"(r0), "r"(r1), "r"(r2), "r"(r3) : "memory")
#define LDSM4(r, addr) \
    asm volatile("ldmatrix.sync.aligned.m8n8.x4.shared.b16 {%0,%1,%2,%3}, [%4];" \
        : "=r"((r)[0]), "=r"((r)[1]), "=r"((r)[2]), "=r"((r)[3]) : "r"(addr))
#define MMA_F16(d, a, b0, b1) \
    asm volatile("mma.sync.aligned.m16n8k16.row.col.f32.f16.f16.f32 " \
        "{%0,%1,%2,%3}, {%4,%5,%6,%7}, {%8,%9}, {%0,%1,%2,%3};" \
        : "+f"((d)[0]), "+f"((d)[1]), "+f"((d)[2]), "+f"((d)[3]) \
        : "r"((a)[0]), "r"((a)[1]), "r"((a)[2]), "r"((a)[3]), "r"(b0), "r"(b1))
#define CP_ASYNC16(dst, src) \
    asm volatile("cp.async.cg.shared.global [%0], [%1], 16;" :: "r"(dst), "l"(src) : "memory")
#define CP_COMMIT() asm volatile("cp.async.commit_group;" ::: "memory")
#define CP_WAIT(n)  asm volatile("cp.async.wait_group %0;" :: "n"(n) : "memory")
#define SWZ128(off) ((uint32_t)(off) ^ ((((uint32_t)(off)) >> 3) & 0x70u))

// ---- dynamic smem layout (bytes) ----
// A: [krow(4)] planes of 130 px x 64 ci fp16 (rn), stride 16640
// B: 2 buffers of [kw(3)] tiles 64co x 64ci fp16 (8192 B each) = 24 KB/buf
// stats alias B buf1 start (prologue-only); partials inside B buf0, clear of
// the D-tile tail (D ends at 67584; partials at 74752) — both epilogue-only.
#define PLANE 16640
#define SMB_OFF (4 * PLANE)              // 66560
#define SMB_BUF 24576
#define SM_STAT (SMB_OFF + SMB_BUF)      // 91136 = buf1 start (prologue-only)
#define SM_PART (SMB_OFF + 8192)         // 74752, inside buf0 (epilogue-only)
#define SMEM_TOTAL (SMB_OFF + 2 * SMB_BUF)   // 115712

#define NTHREADS 512

// ======================= weight prep: fp32 -> fp16 (rn), transposed ====
// dst layout: [b][tap(kh*3+kw)][co][ci]
__global__ void prep_w_kernel(const float* __restrict__ k1, const float* __restrict__ k2) {
    int gi = blockIdx.x * 256 + threadIdx.x;
    if (gi >= 2 * WSZ) return;
    const float* src; __half* dh; int i;
    if (gi < WSZ) { src = k1; dh = g_w1h; i = gi; }
    else          { src = k2; dh = g_w2h; i = gi - WSZ; }
    int ci = i & 63;
    int co = (i >> 6) & 63;
    int k9 = (i >> 12) % 9;
    int b  = (i >> 12) / 9;
    dh[i] = __float2half_rn(src[(((b * 64 + co) * 64 + ci) * 9) + k9]);
}

// ======================= conv via mma.sync fp16 (1 term) ================
// CTA = (row-pair, batch), 512 threads = 16 warps (4/SMSP).
// Warp tile 32px x 32co: 16 warps = 2 rows x 4 Mtiles x 2 Ntiles.
// A and B plain fp16 (rn). Per (kw,kt): 4 LDSM feed 8 MMAs.
template<int PASS>
__global__ __launch_bounds__(NTHREADS, 1)
void conv_mma_kernel(const float* __restrict__ x_ext) {
    extern __shared__ __align__(1024) char smem[];
    const uint32_t sb = smem_u32(smem);
    const int tid = threadIdx.x, lid = tid & 31, wid = tid >> 5;
    const int rp = blockIdx.x, y0 = rp * 2, b = blockIdx.y;
    const float* src = (PASS == 0) ? x_ext : g_buf1;
    const __half* wh = (PASS == 0) ? g_w1h : g_w2h;
    float* dst = (PASS == 0) ? g_buf1 : g_buf2;

    float* smean = (float*)(smem + SM_STAT);   // aliases B buf1 (prologue only)
    float* srstd = smean + 64;

    if (PASS == 1) {
        if (tid < 64) {
            smean[tid] = g_mean[b * 64 + tid];
            srstd[tid] = g_rstd[b * 64 + tid];
        }
        __syncthreads();
    }

    // ---- B stage issue: all 3 kw (24 KB) into buffer buf ----
    auto issueB = [&](int kh, int buf) {
#pragma unroll
        for (int kw = 0; kw < 3; ++kw) {
            const __half* s = wh + (size_t)(b * 9 + kh * 3 + kw) * 4096;
            const uint32_t dstb = sb + SMB_OFF + buf * SMB_BUF + kw * 8192;
            CP_ASYNC16(dstb + SWZ128(tid * 16), s + tid * 8);
        }
        CP_COMMIT();
    };

    // prologue: B(0) in flight while A stages
    issueB(0, 0);

    // ---------- stage A: 4 kh-rows x 130 px x 64 ci, fp16 rn ----------
    {
        const int px = tid & 127;
        const int cihalf = (tid >> 7) * 16;
        const int ar = px + 1;
#pragma unroll
        for (int krow = 0; krow < 4; ++krow) {
            const int grow = y0 + krow - 1;
            const bool vr = (unsigned)grow < 128u;
            const float* base = src + (size_t)b * CHW + (size_t)(vr ? grow : 0) * WW + px;
            const uint32_t ph = sb + krow * PLANE;
#pragma unroll
            for (int c8 = 0; c8 < 2; ++c8) {
                const int ci0 = cihalf + c8 * 8;
                float v[8];
#pragma unroll
                for (int j = 0; j < 8; ++j) {
                    float t = vr ? __ldg(base + (size_t)(ci0 + j) * HWD) : 0.f;
                    if (PASS == 1 && vr) {
                        t = (t - smean[ci0 + j]) * srstd[ci0 + j];
                        t = t >= 0.f ? t : 0.2f * t;
                    }
                    v[j] = t;
                }
                uint32_t hp[4];
#pragma unroll
                for (int j = 0; j < 4; ++j) {
                    __half2 h2 = __floats2half2_rn(v[2*j], v[2*j+1]);
                    hp[j] = *(uint32_t*)&h2;
                }
                const uint32_t off = SWZ128(ar * 128 + ci0 * 2);
                STS128(hp[0], hp[1], hp[2], hp[3], ph + off);
            }
        }
        if (tid < 64) {    // zero halo rows ar=0 / ar=129, all 4 planes
            const int plane = tid >> 4;
            const int row = (tid & 8) ? 129 : 0;
            const int chunk = tid & 7;
            STS128(0u, 0u, 0u, 0u, sb + plane * PLANE + SWZ128(row * 128 + chunk * 16));
        }
    }

    // ---------- warp tiling: 2 rows x 4 Mtiles(32px) x 2 Ntiles(32co) ----------
    const int rowsel = wid >> 3;
    const int m0 = ((wid >> 1) & 3) * 32;
    const int n0 = (wid & 1) * 32;
    const int la_row = lid & 15;
    const int la_k   = (lid & 16) ? 8 : 0;
    const int lb_n   = (lid & 7) + ((lid & 16) ? 8 : 0);
    const int lb_k   = (lid & 8);

    float acc[2][4][4];
#pragma unroll
    for (int mt = 0; mt < 2; ++mt)
#pragma unroll
        for (int nt = 0; nt < 4; ++nt)
#pragma unroll
            for (int j = 0; j < 4; ++j) acc[mt][nt][j] = 0.f;

#pragma unroll 1
    for (int kh = 0; kh < 3; ++kh) {
        CP_WAIT(0);
        __syncthreads();   // B(kh) visible; prior phase done with other buffer
        if (kh < 2) issueB(kh + 1, (kh + 1) & 1);

        const uint32_t bufbase = sb + SMB_OFF + (kh & 1) * SMB_BUF;
        const uint32_t aplane = sb + (rowsel + kh) * PLANE;

#pragma unroll 1
        for (int kw = 0; kw < 3; ++kw) {
            const uint32_t btile = bufbase + kw * 8192;
            const uint32_t arow = (uint32_t)(m0 + la_row + kw) * 128;
#pragma unroll
            for (int kt = 0; kt < 4; ++kt) {
                const uint32_t kcol = (uint32_t)(kt * 16 + la_k) * 2;
                const uint32_t bcol = (uint32_t)(kt * 16 + lb_k) * 2;
                uint32_t af[2][4];
#pragma unroll
                for (int mt = 0; mt < 2; ++mt) {
                    const uint32_t off = SWZ128(arow + (uint32_t)(mt * 16) * 128 + kcol);
                    LDSM4(af[mt], aplane + off);
                }
                uint32_t bf[2][4];
#pragma unroll
                for (int nt2 = 0; nt2 < 2; ++nt2) {
                    const uint32_t off = SWZ128((uint32_t)(n0 + nt2 * 16 + lb_n) * 128 + bcol);
                    LDSM4(bf[nt2], btile + off);
                }
#pragma unroll
                for (int mt = 0; mt < 2; ++mt)
#pragma unroll
                    for (int nt2 = 0; nt2 < 2; ++nt2) {
                        MMA_F16(acc[mt][nt2 * 2],     af[mt], bf[nt2][0], bf[nt2][1]);
                        MMA_F16(acc[mt][nt2 * 2 + 1], af[mt], bf[nt2][2], bf[nt2][3]);
                    }
            }
        }
        // no trailing sync: next phase's top sync covers buffer-reuse safety
    }
    __syncthreads();   // all LDSM reads of A planes + B buf0 done before aliasing

    // ---------- epilogue: acc -> smem D[2][64][132] -> gmem + IN partials ----
    float* D = (float*)smem;    // aliases A region (+1 KB into B buf0)
    {
        const int pr = lid >> 2, qc = 2 * (lid & 3);
#pragma unroll
        for (int mt = 0; mt < 2; ++mt) {
#pragma unroll
            for (int nt = 0; nt < 4; ++nt) {
                const int opx = m0 + mt * 16 + pr;
                const int co = n0 + nt * 8 + qc;
                float* dr = D + (size_t)(rowsel * 64 + co) * 132;
                dr[opx]            = acc[mt][nt][0];
                dr[132 + opx]      = acc[mt][nt][1];
                dr[opx + 8]        = acc[mt][nt][2];
                dr[132 + opx + 8]  = acc[mt][nt][3];
            }
        }
    }
    __syncthreads();
    {   // coalesced store: 512 threads cover 128 (r,co)-rows x 128 px
        const int row = tid >> 2;            // 0..127 = r*64 + co
        const int r = row >> 6, co = row & 63;
        const int pxb = (tid & 3) * 32;
        float* op = dst + (size_t)b * CHW + (size_t)co * HWD + (y0 + r) * WW + pxb;
        const float* dr = D + (size_t)row * 132 + pxb;
#pragma unroll
        for (int i = 0; i < 8; ++i)
            *(float4*)(op + i * 4) = *(const float4*)(dr + i * 4);
    }
    {   // instance-norm partials: thread t -> (r, co, quarter)
        const int r = tid >> 8, co = (tid >> 2) & 63, q = tid & 3;
        const float* dr = D + (size_t)(r * 64 + co) * 132 + q * 32;
        float s = 0.f, s2 = 0.f;
#pragma unroll
        for (int i = 0; i < 32; ++i) { float v = dr[i]; s += v; s2 += v * v; }
        s  += __shfl_xor_sync(0xffffffffu, s, 1);
        s2 += __shfl_xor_sync(0xffffffffu, s2, 1);
        s  += __shfl_xor_sync(0xffffffffu, s, 2);
        s2 += __shfl_xor_sync(0xffffffffu, s2, 2);
        if (q == 0) {
            float* P = (float*)(smem + SM_PART);   // inside B buf0, past D tail
            P[r * 64 + co]       = s;
            P[128 + r * 64 + co] = s2;
        }
    }
    __syncthreads();
    if (tid < 64) {
        const float* P = (float*)(smem + SM_PART);
        const int g = b * 64 + tid;
        g_psum [g * 64 + rp] = P[tid] + P[64 + tid];
        g_psum2[g * 64 + rp] = P[128 + tid] + P[192 + tid];
    }
}

// ======================= stats reduce: 64 partials per group ============
__global__ void stats_reduce_kernel() {
    const int g = blockIdx.x;
    const int l = threadIdx.x;          // 32 threads
    float s  = g_psum [g * 64 + 2 * l] + g_psum [g * 64 + 2 * l + 1];
    float s2 = g_psum2[g * 64 + 2 * l] + g_psum2[g * 64 + 2 * l + 1];
#pragma unroll
    for (int o = 16; o; o >>= 1) {
        s  += __shfl_xor_sync(0xffffffffu, s, o);
        s2 += __shfl_xor_sync(0xffffffffu, s2, o);
    }
    if (l == 0) {
        const float inv = 1.f / (float)HWD;
        float m = s * inv;
        float var = s2 * inv - m * m;
        g_mean[g] = m;
        g_rstd[g] = rsqrtf(var + 1e-5f);
    }
}

__device__ __forceinline__ float lrelu(float v) { return v >= 0.f ? v : 0.2f * v; }

// ---------- out = lrelu(x + IN(buf2)) ----------
__global__ void final_kernel(const float* __restrict__ x, float* __restrict__ out) {
    const int i = blockIdx.x * 256 + threadIdx.x;      // float4 index
    float4 v  = ((const float4*)g_buf2)[i];
    float4 xv = ((const float4*)x)[i];
    const int g = i >> 12;
    const float m = g_mean[g], rs = g_rstd[g];
    float4 o;
    o.x = lrelu(xv.x + (v.x - m) * rs);
    o.y = lrelu(xv.y + (v.y - m) * rs);
    o.z = lrelu(xv.z + (v.z - m) * rs);
    o.w = lrelu(xv.w + (v.w - m) * rs);
    ((float4*)out)[i] = o;
}

extern "C" void kernel_launch(void* const* d_in, const int* in_sizes, int n_in,
                              void* d_out, int out_size) {
    const float* x  = (const float*)d_in[0];
    const float* k1 = (const float*)d_in[1];
    const float* k2 = (const float*)d_in[2];
    float* out = (float*)d_out;

    cudaFuncSetAttribute(conv_mma_kernel<0>, cudaFuncAttributeMaxDynamicSharedMemorySize, SMEM_TOTAL);
    cudaFuncSetAttribute(conv_mma_kernel<1>, cudaFuncAttributeMaxDynamicSharedMemorySize, SMEM_TOTAL);

    prep_w_kernel<<<(2 * WSZ + 255) / 256, 256>>>(k1, k2);

    dim3 grid(HH / 2, BB);   // (row-pair, batch)
    conv_mma_kernel<0><<<grid, NTHREADS, SMEM_TOTAL>>>(x);
    stats_reduce_kernel<<<NGRP, 32>>>();
    conv_mma_kernel<1><<<grid, NTHREADS, SMEM_TOTAL>>>(x);
    stats_reduce_kernel<<<NGRP, 32>>>();
    final_kernel<<<NELEM / 1024, 256>>>(x, out);
}

// round 14
// speedup vs baseline: 2.1008x; 1.1952x over previous
#include <cuda_runtime.h>
#include <cuda_fp16.h>
#include <cstdint>

#define BB 16
#define CC 64
#define HH 128
#define WW 128
#define HWD (HH*WW)            // 16384
#define CHW (CC*HWD)           // 1048576
#define NELEM (BB*CHW)         // 16777216
#define NGRP (BB*CC)           // 1024
#define WSZ (BB*CC*CC*9)       // 589824

// Scratch (device globals: allocation-free rule)
__device__ float g_buf1[NELEM];
__device__ float g_buf2[NELEM];
__device__ __align__(16) __half g_w1h[WSZ];
__device__ __align__(16) __half g_w2h[WSZ];
__device__ float g_mean[NGRP];
__device__ float g_rstd[NGRP];
__device__ float g_psum[NGRP * 64];    // [group][rowpair]
__device__ float g_psum2[NGRP * 64];

// ======================= PTX helpers (plain compute_103-safe) ==========
__device__ __forceinline__ uint32_t smem_u32(const void* p) {
    uint32_t a;
    asm("{ .reg .u64 t; cvta.to.shared.u64 t, %1; cvt.u32.u64 %0, t; }" : "=r"(a) : "l"(p));
    return a;
}
#define STS128(r0, r1, r2, r3, addr) \
    asm volatile("st.shared.v4.b32 [%0], {%1, %2, %3, %4};" \
        :: "r"(addr), "r"(r0), "r"(r1), "r"(r2), "r"(r3) : "memory")
#define LDSM4(r, addr) \
    asm volatile("ldmatrix.sync.aligned.m8n8.x4.shared.b16 {%0,%1,%2,%3}, [%4];" \
        : "=r"((r)[0]), "=r"((r)[1]), "=r"((r)[2]), "=r"((r)[3]) : "r"(addr))
#define MMA_F16(d, a, b0, b1) \
    asm volatile("mma.sync.aligned.m16n8k16.row.col.f32.f16.f16.f32 " \
        "{%0,%1,%2,%3}, {%4,%5,%6,%7}, {%8,%9}, {%0,%1,%2,%3};" \
        : "+f"((d)[0]), "+f"((d)[1]), "+f"((d)[2]), "+f"((d)[3]) \
        : "r"((a)[0]), "r"((a)[1]), "r"((a)[2]), "r"((a)[3]), "r"(b0), "r"(b1))
#define CP_ASYNC16(dst, src) \
    asm volatile("cp.async.cg.shared.global [%0], [%1], 16;" :: "r"(dst), "l"(src) : "memory")
#define CP_COMMIT() asm volatile("cp.async.commit_group;" ::: "memory")
#define CP_WAIT(n)  asm volatile("cp.async.wait_group %0;" :: "n"(n) : "memory")
#define SWZ128(off) ((uint32_t)(off) ^ ((((uint32_t)(off)) >> 3) & 0x70u))

// ---- dynamic smem layout (bytes), PER CTA (two CTAs co-resident) ----
// A: [krow(4)] planes of 130 px x 64 ci fp16 (rn), stride 16640
// B: 2 buffers of [kw(3)] tiles 64co x 64ci fp16 (8192 B each) = 24 KB/buf
// stats alias B buf1 start (prologue-only); partials inside B buf0, clear of
// the D-tile tail (D ends at 67584; partials at 74752) — both epilogue-only.
#define PLANE 16640
#define SMB_OFF (4 * PLANE)              // 66560
#define SMB_BUF 24576
#define SM_STAT (SMB_OFF + SMB_BUF)      // 91136 = buf1 start (prologue-only)
#define SM_PART (SMB_OFF + 8192)         // 74752, inside buf0 (epilogue-only)
#define SMEM_TOTAL (SMB_OFF + 2 * SMB_BUF)   // 115712 (x2 = 231424 <= 227 KB)

#define NTHREADS 256

// ======================= weight prep: fp32 -> fp16 (rn), transposed ====
// dst layout: [b][tap(kh*3+kw)][co][ci]
__global__ void prep_w_kernel(const float* __restrict__ k1, const float* __restrict__ k2) {
    int gi = blockIdx.x * 256 + threadIdx.x;
    if (gi >= 2 * WSZ) return;
    const float* src; __half* dh; int i;
    if (gi < WSZ) { src = k1; dh = g_w1h; i = gi; }
    else          { src = k2; dh = g_w2h; i = gi - WSZ; }
    int ci = i & 63;
    int co = (i >> 6) & 63;
    int k9 = (i >> 12) % 9;
    int b  = (i >> 12) / 9;
    dh[i] = __float2half_rn(src[(((b * 64 + co) * 64 + ci) * 9) + k9]);
}

// ======================= conv via mma.sync fp16 (1 term) ================
// CTA = (row-pair, batch), 256 threads = 8 warps, 2 CTAs per SM.
// Warp tile 32px x 64co: 8 warps = 2 rows x 4 Mtiles.
// Per (kw,kt): 6 LDSM feed 16 MMAs (192 B/MMA crossbar traffic).
template<int PASS>
__global__ __launch_bounds__(NTHREADS, 2)
void conv_mma_kernel(const float* __restrict__ x_ext) {
    extern __shared__ __align__(1024) char smem[];
    const uint32_t sb = smem_u32(smem);
    const int tid = threadIdx.x, lid = tid & 31, wid = tid >> 5;
    const int rp = blockIdx.x, y0 = rp * 2, b = blockIdx.y;
    const float* src = (PASS == 0) ? x_ext : g_buf1;
    const __half* wh = (PASS == 0) ? g_w1h : g_w2h;
    float* dst = (PASS == 0) ? g_buf1 : g_buf2;

    float* smean = (float*)(smem + SM_STAT);   // aliases B buf1 (prologue only)
    float* srstd = smean + 64;

    if (PASS == 1) {
        if (tid < 64) {
            smean[tid] = g_mean[b * 64 + tid];
            srstd[tid] = g_rstd[b * 64 + tid];
        }
        __syncthreads();
    }

    // ---- B stage issue: all 3 kw (24 KB) into buffer buf ----
    auto issueB = [&](int kh, int buf) {
#pragma unroll
        for (int kw = 0; kw < 3; ++kw) {
            const __half* s = wh + (size_t)(b * 9 + kh * 3 + kw) * 4096;
            const uint32_t dstb = sb + SMB_OFF + buf * SMB_BUF + kw * 8192;
#pragma unroll
            for (int i = 0; i < 2; ++i) {
                const int chunk = i * 256 + tid;   // 0..511 (16B units)
                CP_ASYNC16(dstb + SWZ128(chunk * 16), s + chunk * 8);
            }
        }
        CP_COMMIT();
    };

    // prologue: B(0) in flight while A stages
    issueB(0, 0);

    // ---------- stage A: 4 kh-rows x 130 px x 64 ci, fp16 rn ----------
    {
        const int px = tid & 127;
        const int cihalf = (tid >> 7) * 32;
        const int ar = px + 1;
#pragma unroll
        for (int krow = 0; krow < 4; ++krow) {
            const int grow = y0 + krow - 1;
            const bool vr = (unsigned)grow < 128u;
            const float* base = src + (size_t)b * CHW + (size_t)(vr ? grow : 0) * WW + px;
            const uint32_t ph = sb + krow * PLANE;
#pragma unroll
            for (int c8 = 0; c8 < 4; ++c8) {
                const int ci0 = cihalf + c8 * 8;
                float v[8];
#pragma unroll
                for (int j = 0; j < 8; ++j) {
                    float t = vr ? __ldg(base + (size_t)(ci0 + j) * HWD) : 0.f;
                    if (PASS == 1 && vr) {
                        t = (t - smean[ci0 + j]) * srstd[ci0 + j];
                        t = t >= 0.f ? t : 0.2f * t;
                    }
                    v[j] = t;
                }
                uint32_t hp[4];
#pragma unroll
                for (int j = 0; j < 4; ++j) {
                    __half2 h2 = __floats2half2_rn(v[2*j], v[2*j+1]);
                    hp[j] = *(uint32_t*)&h2;
                }
                const uint32_t off = SWZ128(ar * 128 + ci0 * 2);
                STS128(hp[0], hp[1], hp[2], hp[3], ph + off);
            }
        }
        if (tid < 64) {    // zero halo rows ar=0 / ar=129, all 4 planes
            const int plane = tid >> 4;
            const int row = (tid & 8) ? 129 : 0;
            const int chunk = tid & 7;
            STS128(0u, 0u, 0u, 0u, sb + plane * PLANE + SWZ128(row * 128 + chunk * 16));
        }
    }

    // ---------- warp tiling: 8 warps = 2 rows x 4 Mtiles(32px), 64co ----------
    const int rowsel = wid >> 2;
    const int m0 = (wid & 3) * 32;
    const int la_row = lid & 15;
    const int la_k   = (lid & 16) ? 8 : 0;
    const int lb_n   = (lid & 7) + ((lid & 16) ? 8 : 0);
    const int lb_k   = (lid & 8);

    float acc[2][8][4];
#pragma unroll
    for (int mt = 0; mt < 2; ++mt)
#pragma unroll
        for (int nt = 0; nt < 8; ++nt)
#pragma unroll
            for (int j = 0; j < 4; ++j) acc[mt][nt][j] = 0.f;

#pragma unroll 1
    for (int kh = 0; kh < 3; ++kh) {
        CP_WAIT(0);
        __syncthreads();   // B(kh) visible; prior phase done with other buffer
        if (kh < 2) issueB(kh + 1, (kh + 1) & 1);

        const uint32_t bufbase = sb + SMB_OFF + (kh & 1) * SMB_BUF;
        const uint32_t aplane = sb + (rowsel + kh) * PLANE;

#pragma unroll 1
        for (int kw = 0; kw < 3; ++kw) {
            const uint32_t btile = bufbase + kw * 8192;
            const uint32_t arow = (uint32_t)(m0 + la_row + kw) * 128;
#pragma unroll
            for (int kt = 0; kt < 4; ++kt) {
                const uint32_t kcol = (uint32_t)(kt * 16 + la_k) * 2;
                const uint32_t bcol = (uint32_t)(kt * 16 + lb_k) * 2;
                uint32_t af[2][4];
#pragma unroll
                for (int mt = 0; mt < 2; ++mt) {
                    const uint32_t off = SWZ128(arow + (uint32_t)(mt * 16) * 128 + kcol);
                    LDSM4(af[mt], aplane + off);
                }
                uint32_t bf[4][4];
#pragma unroll
                for (int nt2 = 0; nt2 < 4; ++nt2) {
                    const uint32_t off = SWZ128((uint32_t)(nt2 * 16 + lb_n) * 128 + bcol);
                    LDSM4(bf[nt2], btile + off);
                }
#pragma unroll
                for (int mt = 0; mt < 2; ++mt)
#pragma unroll
                    for (int nt2 = 0; nt2 < 4; ++nt2) {
                        MMA_F16(acc[mt][nt2 * 2],     af[mt], bf[nt2][0], bf[nt2][1]);
                        MMA_F16(acc[mt][nt2 * 2 + 1], af[mt], bf[nt2][2], bf[nt2][3]);
                    }
            }
        }
        // no trailing sync: next phase's top sync covers buffer-reuse safety
    }
    __syncthreads();   // all LDSM reads of A planes + B buf0 done before aliasing

    // ---------- epilogue: acc -> smem D[2][64][132] -> gmem + IN partials ----
    float* D = (float*)smem;    // aliases A region (+1 KB into B buf0)
    {
        const int pr = lid >> 2, qc = 2 * (lid & 3);
#pragma unroll
        for (int mt = 0; mt < 2; ++mt) {
#pragma unroll
            for (int nt = 0; nt < 8; ++nt) {
                const int opx = m0 + mt * 16 + pr;
                const int co = nt * 8 + qc;
                float* dr = D + (size_t)(rowsel * 64 + co) * 132;
                dr[opx]            = acc[mt][nt][0];
                dr[132 + opx]      = acc[mt][nt][1];
                dr[opx + 8]        = acc[mt][nt][2];
                dr[132 + opx + 8]  = acc[mt][nt][3];
            }
        }
    }
    __syncthreads();
    {   // coalesced store: 256 threads cover 128 (r,co)-rows x 128 px
        const int row = tid >> 1;            // 0..127 = r*64 + co
        const int r = row >> 6, co = row & 63;
        const int pxb = (tid & 1) * 64;
        float* op = dst + (size_t)b * CHW + (size_t)co * HWD + (y0 + r) * WW + pxb;
        const float* dr = D + (size_t)row * 132 + pxb;
#pragma unroll
        for (int i = 0; i < 16; ++i)
            *(float4*)(op + i * 4) = *(const float4*)(dr + i * 4);
    }
    {   // instance-norm partials: thread t -> (r, co, half)
        const int r = tid >> 7, co = (tid >> 1) & 63, half = tid & 1;
        const float* dr = D + (size_t)(r * 64 + co) * 132 + half * 64;
        float s = 0.f, s2 = 0.f;
#pragma unroll
        for (int i = 0; i < 64; ++i) { float v = dr[i]; s += v; s2 += v * v; }
        s  += __shfl_xor_sync(0xffffffffu, s, 1);
        s2 += __shfl_xor_sync(0xffffffffu, s2, 1);
        if (half == 0) {
            float* P = (float*)(smem + SM_PART);   // inside B buf0, past D tail
            P[r * 64 + co]       = s;
            P[128 + r * 64 + co] = s2;
        }
    }
    __syncthreads();
    if (tid < 64) {
        const float* P = (float*)(smem + SM_PART);
        const int g = b * 64 + tid;
        g_psum [g * 64 + rp] = P[tid] + P[64 + tid];
        g_psum2[g * 64 + rp] = P[128 + tid] + P[192 + tid];
    }
}

// ======================= stats reduce: 64 partials per group ============
__global__ void stats_reduce_kernel() {
    const int g = blockIdx.x;
    const int l = threadIdx.x;          // 32 threads
    float s  = g_psum [g * 64 + 2 * l] + g_psum [g * 64 + 2 * l + 1];
    float s2 = g_psum2[g * 64 + 2 * l] + g_psum2[g * 64 + 2 * l + 1];
#pragma unroll
    for (int o = 16; o; o >>= 1) {
        s  += __shfl_xor_sync(0xffffffffu, s, o);
        s2 += __shfl_xor_sync(0xffffffffu, s2, o);
    }
    if (l == 0) {
        const float inv = 1.f / (float)HWD;
        float m = s * inv;
        float var = s2 * inv - m * m;
        g_mean[g] = m;
        g_rstd[g] = rsqrtf(var + 1e-5f);
    }
}

__device__ __forceinline__ float lrelu(float v) { return v >= 0.f ? v : 0.2f * v; }

// ---------- out = lrelu(x + IN(buf2)) ----------
__global__ void final_kernel(const float* __restrict__ x, float* __restrict__ out) {
    const int i = blockIdx.x * 256 + threadIdx.x;      // float4 index
    float4 v  = ((const float4*)g_buf2)[i];
    float4 xv = ((const float4*)x)[i];
    const int g = i >> 12;
    const float m = g_mean[g], rs = g_rstd[g];
    float4 o;
    o.x = lrelu(xv.x + (v.x - m) * rs);
    o.y = lrelu(xv.y + (v.y - m) * rs);
    o.z = lrelu(xv.z + (v.z - m) * rs);
    o.w = lrelu(xv.w + (v.w - m) * rs);
    ((float4*)out)[i] = o;
}

extern "C" void kernel_launch(void* const* d_in, const int* in_sizes, int n_in,
                              void* d_out, int out_size) {
    const float* x  = (const float*)d_in[0];
    const float* k1 = (const float*)d_in[1];
    const float* k2 = (const float*)d_in[2];
    float* out = (float*)d_out;

    cudaFuncSetAttribute(conv_mma_kernel<0>, cudaFuncAttributeMaxDynamicSharedMemorySize, SMEM_TOTAL);
    cudaFuncSetAttribute(conv_mma_kernel<1>, cudaFuncAttributeMaxDynamicSharedMemorySize, SMEM_TOTAL);

    prep_w_kernel<<<(2 * WSZ + 255) / 256, 256>>>(k1, k2);

    dim3 grid(HH / 2, BB);   // (row-pair, batch)
    conv_mma_kernel<0><<<grid, NTHREADS, SMEM_TOTAL>>>(x);
    stats_reduce_kernel<<<NGRP, 32>>>();
    conv_mma_kernel<1><<<grid, NTHREADS, SMEM_TOTAL>>>(x);
    stats_reduce_kernel<<<NGRP, 32>>>();
    final_kernel<<<NELEM / 1024, 256>>>(x, out);
}

// round 15
// speedup vs baseline: 2.1568x; 1.0266x over previous
#include <cuda_runtime.h>
#include <cuda_fp16.h>
#include <cstdint>

#define BB 16
#define CC 64
#define HH 128
#define WW 128
#define HWD (HH*WW)            // 16384
#define CHW (CC*HWD)           // 1048576
#define NELEM (BB*CHW)         // 16777216
#define NGRP (BB*CC)           // 1024
#define WSZ (BB*CC*CC*9)       // 589824

// Scratch (device globals: allocation-free rule)
__device__ float g_buf1[NELEM];
__device__ float g_buf2[NELEM];
__device__ __align__(16) __half g_w1h[WSZ];
__device__ __align__(16) __half g_w2h[WSZ];
__device__ float g_mean[NGRP];
__device__ float g_rstd[NGRP];
__device__ float g_psum[NGRP * 64];    // [group][rowpair]
__device__ float g_psum2[NGRP * 64];

// ======================= PTX helpers (plain compute_103-safe) ==========
__device__ __forceinline__ uint32_t smem_u32(const void* p) {
    uint32_t a;
    asm("{ .reg .u64 t; cvta.to.shared.u64 t, %1; cvt.u32.u64 %0, t; }" : "=r"(a) : "l"(p));
    return a;
}
#define STS128(r0, r1, r2, r3, addr) \
    asm volatile("st.shared.v4.b32 [%0], {%1, %2, %3, %4};" \
        :: "r"(addr), "r"(r0), "r"(r1), "r"(r2), "r"(r3) : "memory")
#define LDSM4(r, addr) \
    asm volatile("ldmatrix.sync.aligned.m8n8.x4.shared.b16 {%0,%1,%2,%3}, [%4];" \
        : "=r"((r)[0]), "=r"((r)[1]), "=r"((r)[2]), "=r"((r)[3]) : "r"(addr))
#define MMA_F16(d, a, b0, b1) \
    asm volatile("mma.sync.aligned.m16n8k16.row.col.f32.f16.f16.f32 " \
        "{%0,%1,%2,%3}, {%4,%5,%6,%7}, {%8,%9}, {%0,%1,%2,%3};" \
        : "+f"((d)[0]), "+f"((d)[1]), "+f"((d)[2]), "+f"((d)[3]) \
        : "r"((a)[0]), "r"((a)[1]), "r"((a)[2]), "r"((a)[3]), "r"(b0), "r"(b1))
#define CP_ASYNC16(dst, src) \
    asm volatile("cp.async.cg.shared.global [%0], [%1], 16;" :: "r"(dst), "l"(src) : "memory")
#define CP_COMMIT() asm volatile("cp.async.commit_group;" ::: "memory")
#define CP_WAIT(n)  asm volatile("cp.async.wait_group %0;" :: "n"(n) : "memory")
#define SWZ128(off) ((uint32_t)(off) ^ ((((uint32_t)(off)) >> 3) & 0x70u))

// ---- dynamic smem layout (bytes), PER CTA (two CTAs co-resident) ----
#define PLANE 16640
#define SMB_OFF (4 * PLANE)              // 66560
#define SMB_BUF 24576
#define SM_STAT (SMB_OFF + SMB_BUF)      // 91136 = buf1 start (prologue-only)
#define SM_PART (SMB_OFF + 8192)         // 74752, inside buf0 (epilogue-only)
#define SMEM_TOTAL (SMB_OFF + 2 * SMB_BUF)   // 115712 (x2 = 231424 <= 227 KB)

#define NTHREADS 256

// ======================= weight prep: fp32 -> fp16 (rn), transposed ====
// dst layout: [b][tap(kh*3+kw)][co][ci]
__global__ void prep_w_kernel(const float* __restrict__ k1, const float* __restrict__ k2) {
    int gi = blockIdx.x * 256 + threadIdx.x;
    if (gi >= 2 * WSZ) return;
    const float* src; __half* dh; int i;
    if (gi < WSZ) { src = k1; dh = g_w1h; i = gi; }
    else          { src = k2; dh = g_w2h; i = gi - WSZ; }
    int ci = i & 63;
    int co = (i >> 6) & 63;
    int k9 = (i >> 12) % 9;
    int b  = (i >> 12) / 9;
    dh[i] = __float2half_rn(src[(((b * 64 + co) * 64 + ci) * 9) + k9]);
}

// ======================= conv via mma.sync fp16 (1 term) ================
// CTA = (row-pair, batch), 256 threads = 8 warps, 2 CTAs per SM.
// Warp tile 32px x 64co: 8 warps = 2 rows x 4 Mtiles.
// Addressing strength-reduced: SWZ128(r*128+c) = r*128 + (c ^ ((r&7)*16)),
// with r loop-invariant per kw and c compile-time per kt.
template<int PASS>
__global__ __launch_bounds__(NTHREADS, 2)
void conv_mma_kernel(const float* __restrict__ x_ext) {
    extern __shared__ __align__(1024) char smem[];
    const uint32_t sb = smem_u32(smem);
    const int tid = threadIdx.x, lid = tid & 31, wid = tid >> 5;
    const int rp = blockIdx.x, y0 = rp * 2, b = blockIdx.y;
    const float* src = (PASS == 0) ? x_ext : g_buf1;
    const __half* wh = (PASS == 0) ? g_w1h : g_w2h;
    float* dst = (PASS == 0) ? g_buf1 : g_buf2;

    float* smean = (float*)(smem + SM_STAT);   // aliases B buf1 (prologue only)
    float* srstd = smean + 64;

    if (PASS == 1) {
        if (tid < 64) {
            smean[tid] = g_mean[b * 64 + tid];
            srstd[tid] = g_rstd[b * 64 + tid];
        }
        __syncthreads();
    }

    // ---- B stage issue: all 3 kw (24 KB) into buffer buf ----
    auto issueB = [&](int kh, int buf) {
#pragma unroll
        for (int kw = 0; kw < 3; ++kw) {
            const __half* s = wh + (size_t)(b * 9 + kh * 3 + kw) * 4096;
            const uint32_t dstb = sb + SMB_OFF + buf * SMB_BUF + kw * 8192;
#pragma unroll
            for (int i = 0; i < 2; ++i) {
                const int chunk = i * 256 + tid;   // 0..511 (16B units)
                CP_ASYNC16(dstb + SWZ128(chunk * 16), s + chunk * 8);
            }
        }
        CP_COMMIT();
    };

    // prologue: B(0) in flight while A stages
    issueB(0, 0);

    // ---------- stage A: 4 kh-rows x 130 px x 64 ci, fp16 rn ----------
    {
        const int px = tid & 127;
        const int cihalf = (tid >> 7) * 32;
        const int ar = px + 1;
#pragma unroll
        for (int krow = 0; krow < 4; ++krow) {
            const int grow = y0 + krow - 1;
            const bool vr = (unsigned)grow < 128u;
            const float* base = src + (size_t)b * CHW + (size_t)(vr ? grow : 0) * WW + px;
            const uint32_t ph = sb + krow * PLANE;
#pragma unroll
            for (int c8 = 0; c8 < 4; ++c8) {
                const int ci0 = cihalf + c8 * 8;
                float v[8];
#pragma unroll
                for (int j = 0; j < 8; ++j) {
                    float t = vr ? __ldg(base + (size_t)(ci0 + j) * HWD) : 0.f;
                    if (PASS == 1 && vr) {
                        t = (t - smean[ci0 + j]) * srstd[ci0 + j];
                        t = t >= 0.f ? t : 0.2f * t;
                    }
                    v[j] = t;
                }
                uint32_t hp[4];
#pragma unroll
                for (int j = 0; j < 4; ++j) {
                    __half2 h2 = __floats2half2_rn(v[2*j], v[2*j+1]);
                    hp[j] = *(uint32_t*)&h2;
                }
                const uint32_t off = SWZ128(ar * 128 + ci0 * 2);
                STS128(hp[0], hp[1], hp[2], hp[3], ph + off);
            }
        }
        if (tid < 64) {    // zero halo rows ar=0 / ar=129, all 4 planes
            const int plane = tid >> 4;
            const int row = (tid & 8) ? 129 : 0;
            const int chunk = tid & 7;
            STS128(0u, 0u, 0u, 0u, sb + plane * PLANE + SWZ128(row * 128 + chunk * 16));
        }
    }

    // ---------- warp tiling: 8 warps = 2 rows x 4 Mtiles(32px), 64co ----------
    const int rowsel = wid >> 2;
    const int m0 = (wid & 3) * 32;
    const int la_row = lid & 15;
    const int la_k   = (lid & 16) ? 8 : 0;
    const int lb_n   = (lid & 7) + ((lid & 16) ? 8 : 0);
    const int lb_k   = (lid & 8);

    // phase-invariant B addressing: row offsets + swizzle-xored k-columns
    const uint32_t key_b = ((uint32_t)lb_n & 7u) * 16u;
    uint32_t browoff[4], bxor[4];
#pragma unroll
    for (int nt2 = 0; nt2 < 4; ++nt2)
        browoff[nt2] = (uint32_t)(lb_n + nt2 * 16) * 128u;
#pragma unroll
    for (int kt = 0; kt < 4; ++kt)
        bxor[kt] = ((uint32_t)(kt * 16 + lb_k) * 2u) ^ key_b;

    const int ar0 = m0 + la_row;   // A row base (add kw per tap)

    float acc[2][8][4];
#pragma unroll
    for (int mt = 0; mt < 2; ++mt)
#pragma unroll
        for (int nt = 0; nt < 8; ++nt)
#pragma unroll
            for (int j = 0; j < 4; ++j) acc[mt][nt][j] = 0.f;

#pragma unroll 1
    for (int kh = 0; kh < 3; ++kh) {
        CP_WAIT(0);
        __syncthreads();   // B(kh) visible; prior phase done with other buffer
        if (kh < 2) issueB(kh + 1, (kh + 1) & 1);

        const uint32_t bufbase = sb + SMB_OFF + (kh & 1) * SMB_BUF;
        const uint32_t aplane = sb + (rowsel + kh) * PLANE;

#pragma unroll
        for (int kw = 0; kw < 3; ++kw) {
            const uint32_t btile = bufbase + (uint32_t)kw * 8192u;
            const int arw = ar0 + kw;
            const uint32_t abase = aplane + (uint32_t)arw * 128u;
            const uint32_t akey = ((uint32_t)arw & 7u) * 16u;
#pragma unroll
            for (int kt = 0; kt < 4; ++kt) {
                const uint32_t axor = ((uint32_t)(kt * 16 + la_k) * 2u) ^ akey;
                uint32_t af[2][4];
                LDSM4(af[0], abase + axor);
                LDSM4(af[1], abase + 2048u + axor);
                uint32_t bf[4][4];
#pragma unroll
                for (int nt2 = 0; nt2 < 4; ++nt2)
                    LDSM4(bf[nt2], btile + browoff[nt2] + bxor[kt]);
#pragma unroll
                for (int mt = 0; mt < 2; ++mt)
#pragma unroll
                    for (int nt2 = 0; nt2 < 4; ++nt2) {
                        MMA_F16(acc[mt][nt2 * 2],     af[mt], bf[nt2][0], bf[nt2][1]);
                        MMA_F16(acc[mt][nt2 * 2 + 1], af[mt], bf[nt2][2], bf[nt2][3]);
                    }
            }
        }
        // no trailing sync: next phase's top sync covers buffer-reuse safety
    }
    __syncthreads();   // all LDSM reads of A planes + B buf0 done before aliasing

    // ---------- epilogue: acc -> smem D[2][64][132] -> gmem + IN partials ----
    float* D = (float*)smem;    // aliases A region (+1 KB into B buf0)
    {
        const int pr = lid >> 2, qc = 2 * (lid & 3);
#pragma unroll
        for (int mt = 0; mt < 2; ++mt) {
#pragma unroll
            for (int nt = 0; nt < 8; ++nt) {
                const int opx = m0 + mt * 16 + pr;
                const int co = nt * 8 + qc;
                float* dr = D + (size_t)(rowsel * 64 + co) * 132;
                dr[opx]            = acc[mt][nt][0];
                dr[132 + opx]      = acc[mt][nt][1];
                dr[opx + 8]        = acc[mt][nt][2];
                dr[132 + opx + 8]  = acc[mt][nt][3];
            }
        }
    }
    __syncthreads();
    {   // coalesced store: 256 threads cover 128 (r,co)-rows x 128 px
        const int row = tid >> 1;            // 0..127 = r*64 + co
        const int r = row >> 6, co = row & 63;
        const int pxb = (tid & 1) * 64;
        float* op = dst + (size_t)b * CHW + (size_t)co * HWD + (y0 + r) * WW + pxb;
        const float* dr = D + (size_t)row * 132 + pxb;
#pragma unroll
        for (int i = 0; i < 16; ++i)
            *(float4*)(op + i * 4) = *(const float4*)(dr + i * 4);
    }
    {   // instance-norm partials: thread t -> (r, co, half)
        const int r = tid >> 7, co = (tid >> 1) & 63, half = tid & 1;
        const float* dr = D + (size_t)(r * 64 + co) * 132 + half * 64;
        float s = 0.f, s2 = 0.f;
#pragma unroll
        for (int i = 0; i < 64; ++i) { float v = dr[i]; s += v; s2 += v * v; }
        s  += __shfl_xor_sync(0xffffffffu, s, 1);
        s2 += __shfl_xor_sync(0xffffffffu, s2, 1);
        if (half == 0) {
            float* P = (float*)(smem + SM_PART);   // inside B buf0, past D tail
            P[r * 64 + co]       = s;
            P[128 + r * 64 + co] = s2;
        }
    }
    __syncthreads();
    if (tid < 64) {
        const float* P = (float*)(smem + SM_PART);
        const int g = b * 64 + tid;
        g_psum [g * 64 + rp] = P[tid] + P[64 + tid];
        g_psum2[g * 64 + rp] = P[128 + tid] + P[192 + tid];
    }
}

// ======================= stats reduce: 64 partials per group ============
__global__ void stats_reduce_kernel() {
    const int g = blockIdx.x;
    const int l = threadIdx.x;          // 32 threads
    float s  = g_psum [g * 64 + 2 * l] + g_psum [g * 64 + 2 * l + 1];
    float s2 = g_psum2[g * 64 + 2 * l] + g_psum2[g * 64 + 2 * l + 1];
#pragma unroll
    for (int o = 16; o; o >>= 1) {
        s  += __shfl_xor_sync(0xffffffffu, s, o);
        s2 += __shfl_xor_sync(0xffffffffu, s2, o);
    }
    if (l == 0) {
        const float inv = 1.f / (float)HWD;
        float m = s * inv;
        float var = s2 * inv - m * m;
        g_mean[g] = m;
        g_rstd[g] = rsqrtf(var + 1e-5f);
    }
}

__device__ __forceinline__ float lrelu(float v) { return v >= 0.f ? v : 0.2f * v; }

// ---------- out = lrelu(x + IN(buf2)) ----------
__global__ void final_kernel(const float* __restrict__ x, float* __restrict__ out) {
    const int i = blockIdx.x * 256 + threadIdx.x;      // float4 index
    float4 v  = ((const float4*)g_buf2)[i];
    float4 xv = ((const float4*)x)[i];
    const int g = i >> 12;
    const float m = g_mean[g], rs = g_rstd[g];
    float4 o;
    o.x = lrelu(xv.x + (v.x - m) * rs);
    o.y = lrelu(xv.y + (v.y - m) * rs);
    o.z = lrelu(xv.z + (v.z - m) * rs);
    o.w = lrelu(xv.w + (v.w - m) * rs);
    ((float4*)out)[i] = o;
}

extern "C" void kernel_launch(void* const* d_in, const int* in_sizes, int n_in,
                              void* d_out, int out_size) {
    const float* x  = (const float*)d_in[0];
    const float* k1 = (const float*)d_in[1];
    const float* k2 = (const float*)d_in[2];
    float* out = (float*)d_out;

    cudaFuncSetAttribute(conv_mma_kernel<0>, cudaFuncAttributeMaxDynamicSharedMemorySize, SMEM_TOTAL);
    cudaFuncSetAttribute(conv_mma_kernel<1>, cudaFuncAttributeMaxDynamicSharedMemorySize, SMEM_TOTAL);

    prep_w_kernel<<<(2 * WSZ + 255) / 256, 256>>>(k1, k2);

    dim3 grid(HH / 2, BB);   // (row-pair, batch)
    conv_mma_kernel<0><<<grid, NTHREADS, SMEM_TOTAL>>>(x);
    stats_reduce_kernel<<<NGRP, 32>>>();
    conv_mma_kernel<1><<<grid, NTHREADS, SMEM_TOTAL>>>(x);
    stats_reduce_kernel<<<NGRP, 32>>>();
    final_kernel<<<NELEM / 1024, 256>>>(x, out);
}

// round 16
// speedup vs baseline: 2.2756x; 1.0551x over previous
#include <cuda_runtime.h>
#include <cuda_fp16.h>
#include <cstdint>

#define BB 16
#define CC 64
#define HH 128
#define WW 128
#define HWD (HH*WW)            // 16384
#define CHW (CC*HWD)           // 1048576
#define NELEM (BB*CHW)         // 16777216
#define NGRP (BB*CC)           // 1024
#define WSZ (BB*CC*CC*9)       // 589824

// Scratch (device globals: allocation-free rule). Intermediates are fp16.
__device__ __align__(16) __half g_buf1h[NELEM];
__device__ __align__(16) __half g_buf2h[NELEM];
__device__ __align__(16) __half g_w1h[WSZ];
__device__ __align__(16) __half g_w2h[WSZ];
__device__ float g_mean[NGRP];
__device__ float g_rstd[NGRP];
__device__ float g_psum[NGRP * 64];    // [group][rowpair]
__device__ float g_psum2[NGRP * 64];

// ======================= PTX helpers (plain compute_103-safe) ==========
__device__ __forceinline__ uint32_t smem_u32(const void* p) {
    uint32_t a;
    asm("{ .reg .u64 t; cvta.to.shared.u64 t, %1; cvt.u32.u64 %0, t; }" : "=r"(a) : "l"(p));
    return a;
}
#define STS128(r0, r1, r2, r3, addr) \
    asm volatile("st.shared.v4.b32 [%0], {%1, %2, %3, %4};" \
        :: "r"(addr), "r"(r0), "r"(r1), "r"(r2), "r"(r3) : "memory")
#define LDSM4(r, addr) \
    asm volatile("ldmatrix.sync.aligned.m8n8.x4.shared.b16 {%0,%1,%2,%3}, [%4];" \
        : "=r"((r)[0]), "=r"((r)[1]), "=r"((r)[2]), "=r"((r)[3]) : "r"(addr))
#define MMA_F16(d, a, b0, b1) \
    asm volatile("mma.sync.aligned.m16n8k16.row.col.f32.f16.f16.f32 " \
        "{%0,%1,%2,%3}, {%4,%5,%6,%7}, {%8,%9}, {%0,%1,%2,%3};" \
        : "+f"((d)[0]), "+f"((d)[1]), "+f"((d)[2]), "+f"((d)[3]) \
        : "r"((a)[0]), "r"((a)[1]), "r"((a)[2]), "r"((a)[3]), "r"(b0), "r"(b1))
#define CP_ASYNC16(dst, src) \
    asm volatile("cp.async.cg.shared.global [%0], [%1], 16;" :: "r"(dst), "l"(src) : "memory")
#define CP_COMMIT() asm volatile("cp.async.commit_group;" ::: "memory")
#define CP_WAIT(n)  asm volatile("cp.async.wait_group %0;" :: "n"(n) : "memory")
#define SWZ128(off) ((uint32_t)(off) ^ ((((uint32_t)(off)) >> 3) & 0x70u))

// ---- dynamic smem layout (bytes), PER CTA (two CTAs co-resident) ----
#define PLANE 16640
#define SMB_OFF (4 * PLANE)              // 66560
#define SMB_BUF 24576
#define SM_STAT (SMB_OFF + SMB_BUF)      // 91136 = buf1 start (prologue-only)
#define SM_PART (SMB_OFF + 8192)         // 74752, inside buf0 (epilogue-only)
#define SMEM_TOTAL (SMB_OFF + 2 * SMB_BUF)   // 115712 (x2 = 231424 <= 227 KB)

#define NTHREADS 256
#define DSTRIDE 168      // fp16 D-tile row stride (336 B: 16B-aligned, 8-bank spread)

// ======================= weight prep: fp32 -> fp16 (rn), transposed ====
// dst layout: [b][tap(kh*3+kw)][co][ci]
__global__ void prep_w_kernel(const float* __restrict__ k1, const float* __restrict__ k2) {
    int gi = blockIdx.x * 256 + threadIdx.x;
    if (gi >= 2 * WSZ) return;
    const float* src; __half* dh; int i;
    if (gi < WSZ) { src = k1; dh = g_w1h; i = gi; }
    else          { src = k2; dh = g_w2h; i = gi - WSZ; }
    int ci = i & 63;
    int co = (i >> 6) & 63;
    int k9 = (i >> 12) % 9;
    int b  = (i >> 12) / 9;
    dh[i] = __float2half_rn(src[(((b * 64 + co) * 64 + ci) * 9) + k9]);
}

// ======================= conv via mma.sync fp16 (1 term) ================
// CTA = (row-pair, batch), 256 threads = 8 warps, 2 CTAs per SM.
// Warp tile 32px x 64co. fp16 in/out; fp16 D-tile epilogue.
template<int PASS>
__global__ __launch_bounds__(NTHREADS, 2)
void conv_mma_kernel(const float* __restrict__ x_ext) {
    extern __shared__ __align__(1024) char smem[];
    const uint32_t sb = smem_u32(smem);
    const int tid = threadIdx.x, lid = tid & 31, wid = tid >> 5;
    const int rp = blockIdx.x, y0 = rp * 2, b = blockIdx.y;
    const __half* wh = (PASS == 0) ? g_w1h : g_w2h;
    __half* dst = (PASS == 0) ? g_buf1h : g_buf2h;

    float* smean = (float*)(smem + SM_STAT);   // aliases B buf1 (prologue only)
    float* srstd = smean + 64;

    if (PASS == 1) {
        if (tid < 64) {
            smean[tid] = g_mean[b * 64 + tid];
            srstd[tid] = g_rstd[b * 64 + tid];
        }
        __syncthreads();
    }

    // ---- B stage issue: all 3 kw (24 KB) into buffer buf ----
    auto issueB = [&](int kh, int buf) {
#pragma unroll
        for (int kw = 0; kw < 3; ++kw) {
            const __half* s = wh + (size_t)(b * 9 + kh * 3 + kw) * 4096;
            const uint32_t dstb = sb + SMB_OFF + buf * SMB_BUF + kw * 8192;
#pragma unroll
            for (int i = 0; i < 2; ++i) {
                const int chunk = i * 256 + tid;   // 0..511 (16B units)
                CP_ASYNC16(dstb + SWZ128(chunk * 16), s + chunk * 8);
            }
        }
        CP_COMMIT();
    };

    // prologue: B(0) in flight while A stages
    issueB(0, 0);

    // ---------- stage A: 4 kh-rows x 130 px x 64 ci, fp16 rn ----------
    {
        const int px = tid & 127;
        const int cihalf = (tid >> 7) * 32;
        const int ar = px + 1;
#pragma unroll
        for (int krow = 0; krow < 4; ++krow) {
            const int grow = y0 + krow - 1;
            const bool vr = (unsigned)grow < 128u;
            const size_t boff = (size_t)b * CHW + (size_t)(vr ? grow : 0) * WW + px;
            const uint32_t ph = sb + krow * PLANE;
#pragma unroll
            for (int c8 = 0; c8 < 4; ++c8) {
                const int ci0 = cihalf + c8 * 8;
                uint32_t hp[4];
                if (PASS == 0) {
                    const float* base = x_ext + boff;
                    float v[8];
#pragma unroll
                    for (int j = 0; j < 8; ++j)
                        v[j] = vr ? __ldg(base + (size_t)(ci0 + j) * HWD) : 0.f;
#pragma unroll
                    for (int j = 0; j < 4; ++j) {
                        __half2 h2 = __floats2half2_rn(v[2*j], v[2*j+1]);
                        hp[j] = *(uint32_t*)&h2;
                    }
                } else {
                    const __half* base = g_buf1h + boff;
#pragma unroll
                    for (int j = 0; j < 4; ++j) {
                        float t0 = vr ? __half2float(__ldg(base + (size_t)(ci0 + 2*j) * HWD)) : 0.f;
                        float t1 = vr ? __half2float(__ldg(base + (size_t)(ci0 + 2*j + 1) * HWD)) : 0.f;
                        if (vr) {
                            t0 = (t0 - smean[ci0 + 2*j])     * srstd[ci0 + 2*j];
                            t1 = (t1 - smean[ci0 + 2*j + 1]) * srstd[ci0 + 2*j + 1];
                            t0 = t0 >= 0.f ? t0 : 0.2f * t0;
                            t1 = t1 >= 0.f ? t1 : 0.2f * t1;
                        }
                        __half2 h2 = __floats2half2_rn(t0, t1);
                        hp[j] = *(uint32_t*)&h2;
                    }
                }
                const uint32_t off = SWZ128(ar * 128 + ci0 * 2);
                STS128(hp[0], hp[1], hp[2], hp[3], ph + off);
            }
        }
        if (tid < 64) {    // zero halo rows ar=0 / ar=129, all 4 planes
            const int plane = tid >> 4;
            const int row = (tid & 8) ? 129 : 0;
            const int chunk = tid & 7;
            STS128(0u, 0u, 0u, 0u, sb + plane * PLANE + SWZ128(row * 128 + chunk * 16));
        }
    }

    // ---------- warp tiling: 8 warps = 2 rows x 4 Mtiles(32px), 64co ----------
    const int rowsel = wid >> 2;
    const int m0 = (wid & 3) * 32;
    const int la_row = lid & 15;
    const int la_k   = (lid & 16) ? 8 : 0;
    const int lb_n   = (lid & 7) + ((lid & 16) ? 8 : 0);
    const int lb_k   = (lid & 8);

    // phase-invariant B addressing
    const uint32_t key_b = ((uint32_t)lb_n & 7u) * 16u;
    uint32_t browoff[4], bxor[4];
#pragma unroll
    for (int nt2 = 0; nt2 < 4; ++nt2)
        browoff[nt2] = (uint32_t)(lb_n + nt2 * 16) * 128u;
#pragma unroll
    for (int kt = 0; kt < 4; ++kt)
        bxor[kt] = ((uint32_t)(kt * 16 + lb_k) * 2u) ^ key_b;

    const int ar0 = m0 + la_row;

    float acc[2][8][4];
#pragma unroll
    for (int mt = 0; mt < 2; ++mt)
#pragma unroll
        for (int nt = 0; nt < 8; ++nt)
#pragma unroll
            for (int j = 0; j < 4; ++j) acc[mt][nt][j] = 0.f;

#pragma unroll 1
    for (int kh = 0; kh < 3; ++kh) {
        CP_WAIT(0);
        __syncthreads();   // B(kh) visible; prior phase done with other buffer
        if (kh < 2) issueB(kh + 1, (kh + 1) & 1);

        const uint32_t bufbase = sb + SMB_OFF + (kh & 1) * SMB_BUF;
        const uint32_t aplane = sb + (rowsel + kh) * PLANE;

#pragma unroll
        for (int kw = 0; kw < 3; ++kw) {
            const uint32_t btile = bufbase + (uint32_t)kw * 8192u;
            const int arw = ar0 + kw;
            const uint32_t abase = aplane + (uint32_t)arw * 128u;
            const uint32_t akey = ((uint32_t)arw & 7u) * 16u;
#pragma unroll
            for (int kt = 0; kt < 4; ++kt) {
                const uint32_t axor = ((uint32_t)(kt * 16 + la_k) * 2u) ^ akey;
                uint32_t af[2][4];
                LDSM4(af[0], abase + axor);
                LDSM4(af[1], abase + 2048u + axor);
                uint32_t bf[4][4];
#pragma unroll
                for (int nt2 = 0; nt2 < 4; ++nt2)
                    LDSM4(bf[nt2], btile + browoff[nt2] + bxor[kt]);
#pragma unroll
                for (int mt = 0; mt < 2; ++mt)
#pragma unroll
                    for (int nt2 = 0; nt2 < 4; ++nt2) {
                        MMA_F16(acc[mt][nt2 * 2],     af[mt], bf[nt2][0], bf[nt2][1]);
                        MMA_F16(acc[mt][nt2 * 2 + 1], af[mt], bf[nt2][2], bf[nt2][3]);
                    }
            }
        }
        // no trailing sync: next phase's top sync covers buffer-reuse safety
    }
    __syncthreads();   // all LDSM reads of A planes + B buf0 done before aliasing

    // ---------- epilogue: acc -> fp16 D[128][DSTRIDE] -> gmem + IN partials ----
    __half* D = (__half*)smem;    // aliases A region (43 KB < SMB_OFF)
    {
        const int pr = lid >> 2, qc = 2 * (lid & 3);
#pragma unroll
        for (int mt = 0; mt < 2; ++mt) {
#pragma unroll
            for (int nt = 0; nt < 8; ++nt) {
                const int opx = m0 + mt * 16 + pr;
                const int co = nt * 8 + qc;
                __half* dr = D + (size_t)(rowsel * 64 + co) * DSTRIDE;
                dr[opx]                 = __float2half_rn(acc[mt][nt][0]);
                dr[DSTRIDE + opx]       = __float2half_rn(acc[mt][nt][1]);
                dr[opx + 8]             = __float2half_rn(acc[mt][nt][2]);
                dr[DSTRIDE + opx + 8]   = __float2half_rn(acc[mt][nt][3]);
            }
        }
    }
    __syncthreads();
    {   // coalesced store: 256 threads cover 128 (r,co)-rows x 128 px, fp16
        const int row = tid >> 1;            // 0..127 = r*64 + co
        const int r = row >> 6, co = row & 63;
        const int pxb = (tid & 1) * 64;
        __half* op = dst + (size_t)b * CHW + (size_t)co * HWD + (y0 + r) * WW + pxb;
        const __half* dr = D + (size_t)row * DSTRIDE + pxb;
#pragma unroll
        for (int i = 0; i < 8; ++i)
            *(uint4*)(op + i * 8) = *(const uint4*)(dr + i * 8);
    }
    {   // instance-norm partials: thread t -> (r, co, half)
        const int r = tid >> 7, co = (tid >> 1) & 63, half = tid & 1;
        const __half* dr = D + (size_t)(r * 64 + co) * DSTRIDE + half * 64;
        float s = 0.f, s2 = 0.f;
#pragma unroll
        for (int i = 0; i < 32; ++i) {
            float2 f = __half22float2(*(const __half2*)(dr + 2 * i));
            s += f.x + f.y; s2 += f.x * f.x + f.y * f.y;
        }
        s  += __shfl_xor_sync(0xffffffffu, s, 1);
        s2 += __shfl_xor_sync(0xffffffffu, s2, 1);
        if (half == 0) {
            float* P = (float*)(smem + SM_PART);   // inside B buf0, past D tail
            P[r * 64 + co]       = s;
            P[128 + r * 64 + co] = s2;
        }
    }
    __syncthreads();
    if (tid < 64) {
        const float* P = (float*)(smem + SM_PART);
        const int g = b * 64 + tid;
        g_psum [g * 64 + rp] = P[tid] + P[64 + tid];
        g_psum2[g * 64 + rp] = P[128 + tid] + P[192 + tid];
    }
}

// ======================= stats reduce: 64 partials per group ============
__global__ void stats_reduce_kernel() {
    const int g = blockIdx.x;
    const int l = threadIdx.x;          // 32 threads
    float s  = g_psum [g * 64 + 2 * l] + g_psum [g * 64 + 2 * l + 1];
    float s2 = g_psum2[g * 64 + 2 * l] + g_psum2[g * 64 + 2 * l + 1];
#pragma unroll
    for (int o = 16; o; o >>= 1) {
        s  += __shfl_xor_sync(0xffffffffu, s, o);
        s2 += __shfl_xor_sync(0xffffffffu, s2, o);
    }
    if (l == 0) {
        const float inv = 1.f / (float)HWD;
        float m = s * inv;
        float var = s2 * inv - m * m;
        g_mean[g] = m;
        g_rstd[g] = rsqrtf(var + 1e-5f);
    }
}

__device__ __forceinline__ float lrelu(float v) { return v >= 0.f ? v : 0.2f * v; }

// ---------- out = lrelu(x + IN(buf2)), buf2 fp16 ----------
__global__ void final_kernel(const float* __restrict__ x, float* __restrict__ out) {
    const int i = blockIdx.x * 256 + threadIdx.x;      // 4-element chunk index
    uint2 hv = ((const uint2*)g_buf2h)[i];
    float2 f0 = __half22float2(*(__half2*)&hv.x);
    float2 f1 = __half22float2(*(__half2*)&hv.y);
    float4 xv = ((const float4*)x)[i];
    const int g = i >> 12;
    const float m = g_mean[g], rs = g_rstd[g];
    float4 o;
    o.x = lrelu(xv.x + (f0.x - m) * rs);
    o.y = lrelu(xv.y + (f0.y - m) * rs);
    o.z = lrelu(xv.z + (f1.x - m) * rs);
    o.w = lrelu(xv.w + (f1.y - m) * rs);
    ((float4*)out)[i] = o;
}

extern "C" void kernel_launch(void* const* d_in, const int* in_sizes, int n_in,
                              void* d_out, int out_size) {
    const float* x  = (const float*)d_in[0];
    const float* k1 = (const float*)d_in[1];
    const float* k2 = (const float*)d_in[2];
    float* out = (float*)d_out;

    cudaFuncSetAttribute(conv_mma_kernel<0>, cudaFuncAttributeMaxDynamicSharedMemorySize, SMEM_TOTAL);
    cudaFuncSetAttribute(conv_mma_kernel<1>, cudaFuncAttributeMaxDynamicSharedMemorySize, SMEM_TOTAL);

    prep_w_kernel<<<(2 * WSZ + 255) / 256, 256>>>(k1, k2);

    dim3 grid(HH / 2, BB);   // (row-pair, batch)
    conv_mma_kernel<0><<<grid, NTHREADS, SMEM_TOTAL>>>(x);
    stats_reduce_kernel<<<NGRP, 32>>>();
    conv_mma_kernel<1><<<grid, NTHREADS, SMEM_TOTAL>>>(x);
    stats_reduce_kernel<<<NGRP, 32>>>();
    final_kernel<<<NELEM / 1024, 256>>>(x, out);
}

// round 17
// speedup vs baseline: 2.5942x; 1.1400x over previous
#include <cuda_runtime.h>
#include <cuda_fp16.h>
#include <cstdint>

#define BB 16
#define CC 64
#define HH 128
#define WW 128
#define HWD (HH*WW)            // 16384
#define CHW (CC*HWD)           // 1048576
#define NELEM (BB*CHW)         // 16777216
#define NGRP (BB*CC)           // 1024
#define WSZ (BB*CC*CC*9)       // 589824

// Scratch (device globals: allocation-free rule). Intermediates are fp16.
__device__ __align__(16) __half g_buf1h[NELEM];
__device__ __align__(16) __half g_buf2h[NELEM];
__device__ __align__(16) __half g_w1h[WSZ];
__device__ __align__(16) __half g_w2h[WSZ];
__device__ float g_mean[NGRP];
__device__ float g_rstd[NGRP];
__device__ float g_psum[NGRP * 64];    // [group][rowpair]
__device__ float g_psum2[NGRP * 64];

// ======================= PTX helpers (plain compute_103-safe) ==========
__device__ __forceinline__ uint32_t smem_u32(const void* p) {
    uint32_t a;
    asm("{ .reg .u64 t; cvta.to.shared.u64 t, %1; cvt.u32.u64 %0, t; }" : "=r"(a) : "l"(p));
    return a;
}
#define STS128(r0, r1, r2, r3, addr) \
    asm volatile("st.shared.v4.b32 [%0], {%1, %2, %3, %4};" \
        :: "r"(addr), "r"(r0), "r"(r1), "r"(r2), "r"(r3) : "memory")
#define LDSM4(r, addr) \
    asm volatile("ldmatrix.sync.aligned.m8n8.x4.shared.b16 {%0,%1,%2,%3}, [%4];" \
        : "=r"((r)[0]), "=r"((r)[1]), "=r"((r)[2]), "=r"((r)[3]) : "r"(addr))
#define MMA_F16(d, a, b0, b1) \
    asm volatile("mma.sync.aligned.m16n8k16.row.col.f32.f16.f16.f32 " \
        "{%0,%1,%2,%3}, {%4,%5,%6,%7}, {%8,%9}, {%0,%1,%2,%3};" \
        : "+f"((d)[0]), "+f"((d)[1]), "+f"((d)[2]), "+f"((d)[3]) \
        : "r"((a)[0]), "r"((a)[1]), "r"((a)[2]), "r"((a)[3]), "r"(b0), "r"(b1))
#define CP_ASYNC16(dst, src) \
    asm volatile("cp.async.cg.shared.global [%0], [%1], 16;" :: "r"(dst), "l"(src) : "memory")
#define CP_COMMIT() asm volatile("cp.async.commit_group;" ::: "memory")
#define CP_WAIT(n)  asm volatile("cp.async.wait_group %0;" :: "n"(n) : "memory")
#define SWZ128(off) ((uint32_t)(off) ^ ((((uint32_t)(off)) >> 3) & 0x70u))

// ---- dynamic smem layout (bytes), PER CTA (two CTAs co-resident) ----
#define PLANE 16640
#define SMB_OFF (4 * PLANE)              // 66560
#define SMB_BUF 24576
#define SM_STAT (SMB_OFF + SMB_BUF)      // 91136 = buf1 start (prologue-only)
#define SM_PART (SMB_OFF + 8192)         // 74752, inside buf0 (epilogue-only)
#define SMEM_TOTAL (SMB_OFF + 2 * SMB_BUF)   // 115712 (x2 = 231424 <= 227 KB)

#define NTHREADS 256
#define DSTRIDE 168      // fp16 D-tile row stride (336 B: 16B-aligned, 8-bank spread)

// ======================= weight prep: fp32 -> fp16 (rn), transposed ====
// dst layout: [b][tap(kh*3+kw)][co][ci]
__global__ void prep_w_kernel(const float* __restrict__ k1, const float* __restrict__ k2) {
    int gi = blockIdx.x * 256 + threadIdx.x;
    if (gi >= 2 * WSZ) return;
    const float* src; __half* dh; int i;
    if (gi < WSZ) { src = k1; dh = g_w1h; i = gi; }
    else          { src = k2; dh = g_w2h; i = gi - WSZ; }
    int ci = i & 63;
    int co = (i >> 6) & 63;
    int k9 = (i >> 12) % 9;
    int b  = (i >> 12) / 9;
    dh[i] = __float2half_rn(src[(((b * 64 + co) * 64 + ci) * 9) + k9]);
}

// ======================= conv via mma.sync fp16 (1 term) ================
// CTA = (row-pair, batch), 256 threads = 8 warps, 2 CTAs per SM.
// Warp tile 32px x 64co. fp16 in/out; fp16 D-tile epilogue.
template<int PASS>
__global__ __launch_bounds__(NTHREADS, 2)
void conv_mma_kernel(const float* __restrict__ x_ext) {
    extern __shared__ __align__(1024) char smem[];
    const uint32_t sb = smem_u32(smem);
    const int tid = threadIdx.x, lid = tid & 31, wid = tid >> 5;
    const int rp = blockIdx.x, y0 = rp * 2, b = blockIdx.y;
    const __half* wh = (PASS == 0) ? g_w1h : g_w2h;
    __half* dst = (PASS == 0) ? g_buf1h : g_buf2h;

    float* smean = (float*)(smem + SM_STAT);   // aliases B buf1 (prologue only)
    float* srstd = smean + 64;

    if (PASS == 1) {
        if (tid < 64) {
            smean[tid] = g_mean[b * 64 + tid];
            srstd[tid] = g_rstd[b * 64 + tid];
        }
        __syncthreads();
    }

    // ---- B stage issue: all 3 kw (24 KB) into buffer buf ----
    auto issueB = [&](int kh, int buf) {
#pragma unroll
        for (int kw = 0; kw < 3; ++kw) {
            const __half* s = wh + (size_t)(b * 9 + kh * 3 + kw) * 4096;
            const uint32_t dstb = sb + SMB_OFF + buf * SMB_BUF + kw * 8192;
#pragma unroll
            for (int i = 0; i < 2; ++i) {
                const int chunk = i * 256 + tid;   // 0..511 (16B units)
                CP_ASYNC16(dstb + SWZ128(chunk * 16), s + chunk * 8);
            }
        }
        CP_COMMIT();
    };

    // prologue: B(0) in flight while A stages
    issueB(0, 0);

    // ---------- stage A: 4 kh-rows x 130 px x 64 ci, fp16 rn ----------
    {
        const int px = tid & 127;
        const int cihalf = (tid >> 7) * 32;
        const int ar = px + 1;
#pragma unroll
        for (int krow = 0; krow < 4; ++krow) {
            const int grow = y0 + krow - 1;
            const bool vr = (unsigned)grow < 128u;
            const size_t boff = (size_t)b * CHW + (size_t)(vr ? grow : 0) * WW + px;
            const uint32_t ph = sb + krow * PLANE;
#pragma unroll
            for (int c8 = 0; c8 < 4; ++c8) {
                const int ci0 = cihalf + c8 * 8;
                uint32_t hp[4];
                if (PASS == 0) {
                    const float* base = x_ext + boff;
                    float v[8];
#pragma unroll
                    for (int j = 0; j < 8; ++j)
                        v[j] = vr ? __ldg(base + (size_t)(ci0 + j) * HWD) : 0.f;
#pragma unroll
                    for (int j = 0; j < 4; ++j) {
                        __half2 h2 = __floats2half2_rn(v[2*j], v[2*j+1]);
                        hp[j] = *(uint32_t*)&h2;
                    }
                } else {
                    // batched fp16 loads first (MLP=8), then normalize+pack
                    const __half* base = g_buf1h + boff;
                    __half raw[8];
#pragma unroll
                    for (int j = 0; j < 8; ++j)
                        raw[j] = vr ? __ldg(base + (size_t)(ci0 + j) * HWD) : __half(0.f);
#pragma unroll
                    for (int j = 0; j < 4; ++j) {
                        float t0 = __half2float(raw[2*j]);
                        float t1 = __half2float(raw[2*j + 1]);
                        if (vr) {
                            t0 = (t0 - smean[ci0 + 2*j])     * srstd[ci0 + 2*j];
                            t1 = (t1 - smean[ci0 + 2*j + 1]) * srstd[ci0 + 2*j + 1];
                            t0 = t0 >= 0.f ? t0 : 0.2f * t0;
                            t1 = t1 >= 0.f ? t1 : 0.2f * t1;
                        }
                        __half2 h2 = __floats2half2_rn(t0, t1);
                        hp[j] = *(uint32_t*)&h2;
                    }
                }
                const uint32_t off = SWZ128(ar * 128 + ci0 * 2);
                STS128(hp[0], hp[1], hp[2], hp[3], ph + off);
            }
        }
        if (tid < 64) {    // zero halo rows ar=0 / ar=129, all 4 planes
            const int plane = tid >> 4;
            const int row = (tid & 8) ? 129 : 0;
            const int chunk = tid & 7;
            STS128(0u, 0u, 0u, 0u, sb + plane * PLANE + SWZ128(row * 128 + chunk * 16));
        }
    }

    // ---------- warp tiling: 8 warps = 2 rows x 4 Mtiles(32px), 64co ----------
    const int rowsel = wid >> 2;
    const int m0 = (wid & 3) * 32;
    const int la_row = lid & 15;
    const int la_k   = (lid & 16) ? 8 : 0;
    const int lb_n   = (lid & 7) + ((lid & 16) ? 8 : 0);
    const int lb_k   = (lid & 8);

    // phase-invariant B addressing
    const uint32_t key_b = ((uint32_t)lb_n & 7u) * 16u;
    uint32_t browoff[4], bxor[4];
#pragma unroll
    for (int nt2 = 0; nt2 < 4; ++nt2)
        browoff[nt2] = (uint32_t)(lb_n + nt2 * 16) * 128u;
#pragma unroll
    for (int kt = 0; kt < 4; ++kt)
        bxor[kt] = ((uint32_t)(kt * 16 + lb_k) * 2u) ^ key_b;

    const int ar0 = m0 + la_row;

    float acc[2][8][4];
#pragma unroll
    for (int mt = 0; mt < 2; ++mt)
#pragma unroll
        for (int nt = 0; nt < 8; ++nt)
#pragma unroll
            for (int j = 0; j < 4; ++j) acc[mt][nt][j] = 0.f;

#pragma unroll 1
    for (int kh = 0; kh < 3; ++kh) {
        CP_WAIT(0);
        __syncthreads();   // B(kh) visible; prior phase done with other buffer
        if (kh < 2) issueB(kh + 1, (kh + 1) & 1);

        const uint32_t bufbase = sb + SMB_OFF + (kh & 1) * SMB_BUF;
        const uint32_t aplane = sb + (rowsel + kh) * PLANE;

#pragma unroll
        for (int kw = 0; kw < 3; ++kw) {
            const uint32_t btile = bufbase + (uint32_t)kw * 8192u;
            const int arw = ar0 + kw;
            const uint32_t abase = aplane + (uint32_t)arw * 128u;
            const uint32_t akey = ((uint32_t)arw & 7u) * 16u;
#pragma unroll
            for (int kt = 0; kt < 4; ++kt) {
                const uint32_t axor = ((uint32_t)(kt * 16 + la_k) * 2u) ^ akey;
                uint32_t af[2][4];
                LDSM4(af[0], abase + axor);
                LDSM4(af[1], abase + 2048u + axor);
                uint32_t bf[4][4];
#pragma unroll
                for (int nt2 = 0; nt2 < 4; ++nt2)
                    LDSM4(bf[nt2], btile + browoff[nt2] + bxor[kt]);
#pragma unroll
                for (int mt = 0; mt < 2; ++mt)
#pragma unroll
                    for (int nt2 = 0; nt2 < 4; ++nt2) {
                        MMA_F16(acc[mt][nt2 * 2],     af[mt], bf[nt2][0], bf[nt2][1]);
                        MMA_F16(acc[mt][nt2 * 2 + 1], af[mt], bf[nt2][2], bf[nt2][3]);
                    }
            }
        }
        // no trailing sync: next phase's top sync covers buffer-reuse safety
    }
    __syncthreads();   // all LDSM reads of A planes + B buf0 done before aliasing

    // ---------- epilogue: acc -> fp16 D[128][DSTRIDE] -> gmem + IN partials ----
    __half* D = (__half*)smem;    // aliases A region (43 KB < SMB_OFF)
    {
        const int pr = lid >> 2, qc = 2 * (lid & 3);
#pragma unroll
        for (int mt = 0; mt < 2; ++mt) {
#pragma unroll
            for (int nt = 0; nt < 8; ++nt) {
                const int opx = m0 + mt * 16 + pr;
                const int co = nt * 8 + qc;
                __half* dr = D + (size_t)(rowsel * 64 + co) * DSTRIDE;
                dr[opx]                 = __float2half_rn(acc[mt][nt][0]);
                dr[DSTRIDE + opx]       = __float2half_rn(acc[mt][nt][1]);
                dr[opx + 8]             = __float2half_rn(acc[mt][nt][2]);
                dr[DSTRIDE + opx + 8]   = __float2half_rn(acc[mt][nt][3]);
            }
        }
    }
    __syncthreads();
    {   // coalesced store: 256 threads cover 128 (r,co)-rows x 128 px, fp16
        const int row = tid >> 1;            // 0..127 = r*64 + co
        const int r = row >> 6, co = row & 63;
        const int pxb = (tid & 1) * 64;
        __half* op = dst + (size_t)b * CHW + (size_t)co * HWD + (y0 + r) * WW + pxb;
        const __half* dr = D + (size_t)row * DSTRIDE + pxb;
#pragma unroll
        for (int i = 0; i < 8; ++i)
            *(uint4*)(op + i * 8) = *(const uint4*)(dr + i * 8);
    }
    {   // instance-norm partials: thread t -> (r, co, half)
        const int r = tid >> 7, co = (tid >> 1) & 63, half = tid & 1;
        const __half* dr = D + (size_t)(r * 64 + co) * DSTRIDE + half * 64;
        float s = 0.f, s2 = 0.f;
#pragma unroll
        for (int i = 0; i < 32; ++i) {
            float2 f = __half22float2(*(const __half2*)(dr + 2 * i));
            s += f.x + f.y; s2 += f.x * f.x + f.y * f.y;
        }
        s  += __shfl_xor_sync(0xffffffffu, s, 1);
        s2 += __shfl_xor_sync(0xffffffffu, s2, 1);
        if (half == 0) {
            float* P = (float*)(smem + SM_PART);   // inside B buf0, past D tail
            P[r * 64 + co]       = s;
            P[128 + r * 64 + co] = s2;
        }
    }
    __syncthreads();
    if (tid < 64) {
        const float* P = (float*)(smem + SM_PART);
        const int g = b * 64 + tid;
        g_psum [g * 64 + rp] = P[tid] + P[64 + tid];
        g_psum2[g * 64 + rp] = P[128 + tid] + P[192 + tid];
    }
}

// ======================= stats reduce: 64 partials per group ============
__global__ void stats_reduce_kernel() {
    const int g = blockIdx.x;
    const int l = threadIdx.x;          // 32 threads
    float s  = g_psum [g * 64 + 2 * l] + g_psum [g * 64 + 2 * l + 1];
    float s2 = g_psum2[g * 64 + 2 * l] + g_psum2[g * 64 + 2 * l + 1];
#pragma unroll
    for (int o = 16; o; o >>= 1) {
        s  += __shfl_xor_sync(0xffffffffu, s, o);
        s2 += __shfl_xor_sync(0xffffffffu, s2, o);
    }
    if (l == 0) {
        const float inv = 1.f / (float)HWD;
        float m = s * inv;
        float var = s2 * inv - m * m;
        g_mean[g] = m;
        g_rstd[g] = rsqrtf(var + 1e-5f);
    }
}

__device__ __forceinline__ float lrelu(float v) { return v >= 0.f ? v : 0.2f * v; }

// ---------- out = lrelu(x + IN(buf2)), buf2 fp16 ----------
__global__ void final_kernel(const float* __restrict__ x, float* __restrict__ out) {
    const int i = blockIdx.x * 256 + threadIdx.x;      // 4-element chunk index
    uint2 hv = ((const uint2*)g_buf2h)[i];
    float2 f0 = __half22float2(*(__half2*)&hv.x);
    float2 f1 = __half22float2(*(__half2*)&hv.y);
    float4 xv = ((const float4*)x)[i];
    const int g = i >> 12;
    const float m = g_mean[g], rs = g_rstd[g];
    float4 o;
    o.x = lrelu(xv.x + (f0.x - m) * rs);
    o.y = lrelu(xv.y + (f0.y - m) * rs);
    o.z = lrelu(xv.z + (f1.x - m) * rs);
    o.w = lrelu(xv.w + (f1.y - m) * rs);
    ((float4*)out)[i] = o;
}

extern "C" void kernel_launch(void* const* d_in, const int* in_sizes, int n_in,
                              void* d_out, int out_size) {
    const float* x  = (const float*)d_in[0];
    const float* k1 = (const float*)d_in[1];
    const float* k2 = (const float*)d_in[2];
    float* out = (float*)d_out;

    cudaFuncSetAttribute(conv_mma_kernel<0>, cudaFuncAttributeMaxDynamicSharedMemorySize, SMEM_TOTAL);
    cudaFuncSetAttribute(conv_mma_kernel<1>, cudaFuncAttributeMaxDynamicSharedMemorySize, SMEM_TOTAL);

    prep_w_kernel<<<(2 * WSZ + 255) / 256, 256>>>(k1, k2);

    dim3 grid(HH / 2, BB);   // (row-pair, batch)
    conv_mma_kernel<0><<<grid, NTHREADS, SMEM_TOTAL>>>(x);
    stats_reduce_kernel<<<NGRP, 32>>>();
    conv_mma_kernel<1><<<grid, NTHREADS, SMEM_TOTAL>>>(x);
    stats_reduce_kernel<<<NGRP, 32>>>();
    final_kernel<<<NELEM / 1024, 256>>>(x, out);
}